// round 6
// baseline (speedup 1.0000x reference)
#include <cuda_runtime.h>
#include <cstdint>
#include <math.h>

#define B   64
#define T   512
#define E   512
#define H   1024
#define G4  4096
#define NC  32000
#define VOCABM1 31999

typedef unsigned long long ull;

__device__ __align__(16) float g_x0[(size_t)B * T * E];
__device__ __align__(16) float g_xg[(size_t)B * T * G4];
__device__ __align__(16) float g_h1[(size_t)B * T * H];   // [B][T][H] for L1 proj
__device__ __align__(16) float g_hT[(size_t)T * H * B];   // [t][k/2][b][2] paired
__device__ __align__(16) float g_last[(size_t)B * H];
__device__ int g_seqlen[B];
__device__ unsigned g_bar_count, g_bar_gen;

__device__ __forceinline__ void ffma2(ull& d, ull a, ull b2) {
    asm("fma.rn.f32x2 %0, %1, %2, %0;" : "+l"(d) : "l"(a), "l"(b2));
}
__device__ __forceinline__ ull pk2(float lo, float hi) {
    ull r; asm("mov.b64 %0, {%1, %2};" : "=l"(r) : "f"(lo), "f"(hi)); return r;
}
__device__ __forceinline__ float2 upk(ull v) {
    float2 f; asm("mov.b64 {%0, %1}, %2;" : "=f"(f.x), "=f"(f.y) : "l"(v)); return f;
}
__device__ __forceinline__ float sigm(float x) { return 1.f / (1.f + expf(-x)); }

__global__ void seqlen_kernel(const int* __restrict__ feat, int* __restrict__ out) {
    int b = blockIdx.x, tid = threadIdx.x, cnt = 0;
    for (int t = tid; t < T; t += 256) cnt += (feat[b * T + t] != VOCABM1);
    __shared__ int s[256];
    s[tid] = cnt; __syncthreads();
    for (int o = 128; o > 0; o >>= 1) { if (tid < o) s[tid] += s[tid + o]; __syncthreads(); }
    if (tid == 0) out[b] = s[0] - 1;
}

__global__ void embed_kernel(const int* __restrict__ feat, const float* __restrict__ emb,
                             float* __restrict__ x0) {
    int bt = blockIdx.x;
    int f = feat[bt];
    ((float4*)(x0 + (size_t)bt * E))[threadIdx.x] =
        ((const float4*)(emb + (size_t)f * E))[threadIdx.x];
}

// ---- FFMA2 TN GEMM: C[m][n] = sum_k A[m][k]*W[n][k] + b1[n]+b2[n]
// tile 128x128, 256 thr, 8x8 microtile. M%128==0, N%128==0, K%16==0.
__global__ void __launch_bounds__(256)
gemm2(const float* __restrict__ A, int lda, const float* __restrict__ W, int ldw,
      const float* __restrict__ b1, const float* __restrict__ b2,
      float* __restrict__ C, int ldc, int K) {
    __shared__ float Asd[16 * 256];  // [k][m*2] duplicated
    __shared__ float Bs[16 * 128];   // [k][n]

    const int tid = threadIdx.x;
    const int m0 = blockIdx.y * 128, n0 = blockIdx.x * 128;
    const int ty = tid >> 4, tx = tid & 15;            // 8m x 8n microtile
    const int arow = tid >> 1, kc = (tid & 1) * 8;     // loaders

    const float* Ap = A + (size_t)(m0 + arow) * lda + kc;
    const float* Wp = W + (size_t)(n0 + arow) * ldw + kc;

    ull acc[8][4];
#pragma unroll
    for (int i = 0; i < 8; i++)
#pragma unroll
        for (int j = 0; j < 4; j++) acc[i][j] = 0ULL;

    float4 ra0 = *(const float4*)(Ap), ra1 = *(const float4*)(Ap + 4);
    float4 rb0 = *(const float4*)(Wp), rb1 = *(const float4*)(Wp + 4);

    for (int kt = 0; kt < K; kt += 16) {
        __syncthreads();
        float av[8] = {ra0.x, ra0.y, ra0.z, ra0.w, ra1.x, ra1.y, ra1.z, ra1.w};
        float bv[8] = {rb0.x, rb0.y, rb0.z, rb0.w, rb1.x, rb1.y, rb1.z, rb1.w};
#pragma unroll
        for (int j = 0; j < 8; j++) {
            *(float2*)&Asd[(kc + j) * 256 + arow * 2] = make_float2(av[j], av[j]);
            Bs[(kc + j) * 128 + arow] = bv[j];
        }
        __syncthreads();
        if (kt + 16 < K) {
            ra0 = *(const float4*)(Ap + kt + 16); ra1 = *(const float4*)(Ap + kt + 20);
            rb0 = *(const float4*)(Wp + kt + 16); rb1 = *(const float4*)(Wp + kt + 20);
        }
#pragma unroll
        for (int kk = 0; kk < 16; kk++) {
            const ulonglong2* ap = (const ulonglong2*)&Asd[kk * 256 + ty * 16];
            const ulonglong2* bp = (const ulonglong2*)&Bs[kk * 128 + tx * 8];
            ulonglong2 a0 = ap[0], a1 = ap[1], a2 = ap[2], a3 = ap[3];
            ulonglong2 bb0 = bp[0], bb1 = bp[1];
#define ROWF(i, av_) ffma2(acc[i][0], av_, bb0.x); ffma2(acc[i][1], av_, bb0.y); \
                     ffma2(acc[i][2], av_, bb1.x); ffma2(acc[i][3], av_, bb1.y);
            ROWF(0, a0.x) ROWF(1, a0.y) ROWF(2, a1.x) ROWF(3, a1.y)
            ROWF(4, a2.x) ROWF(5, a2.y) ROWF(6, a3.x) ROWF(7, a3.y)
#undef ROWF
        }
    }

    float bias[8];
    {
        int n = n0 + tx * 8;
#pragma unroll
        for (int j = 0; j < 8; j++) bias[j] = b1[n + j] + b2[n + j];
    }
#pragma unroll
    for (int i = 0; i < 8; i++) {
        float* Cp = C + (size_t)(m0 + ty * 8 + i) * ldc + n0 + tx * 8;
#pragma unroll
        for (int j = 0; j < 4; j++) {
            float2 v = upk(acc[i][j]);
            *(float2*)&Cp[2 * j] = make_float2(v.x + bias[2 * j], v.y + bias[2 * j + 1]);
        }
    }
}

// ---- scalar TN GEMM for FC head (M=64)
__global__ void gemm_tn(const float* __restrict__ A, long lda,
                        const float* __restrict__ W, int ldw,
                        const float* __restrict__ b1,
                        float* __restrict__ C, int ldc, int K) {
    __shared__ float As[16][68];
    __shared__ float Bs[16][68];
    const int tid = threadIdx.x;
    const int m0 = blockIdx.y * 64, n0 = blockIdx.x * 64;
    const float* Ap = A + (long)m0 * lda;
    const float* Wp = W + (long)n0 * ldw;
    const int lr = tid >> 2, lk = (tid & 3) * 4, ty = tid >> 4, tx = tid & 15;
    float acc[4][4];
#pragma unroll
    for (int i = 0; i < 4; i++)
#pragma unroll
        for (int j = 0; j < 4; j++) acc[i][j] = 0.f;
    for (int kt = 0; kt < K; kt += 16) {
        float4 a4 = *(const float4*)(Ap + (long)lr * lda + kt + lk);
        float4 w4 = *(const float4*)(Wp + (long)lr * ldw + kt + lk);
        As[lk + 0][lr] = a4.x; As[lk + 1][lr] = a4.y;
        As[lk + 2][lr] = a4.z; As[lk + 3][lr] = a4.w;
        Bs[lk + 0][lr] = w4.x; Bs[lk + 1][lr] = w4.y;
        Bs[lk + 2][lr] = w4.z; Bs[lk + 3][lr] = w4.w;
        __syncthreads();
#pragma unroll
        for (int kk = 0; kk < 16; kk++) {
            float4 a = *(const float4*)&As[kk][ty * 4];
            float4 b = *(const float4*)&Bs[kk][tx * 4];
            acc[0][0] += a.x*b.x; acc[0][1] += a.x*b.y; acc[0][2] += a.x*b.z; acc[0][3] += a.x*b.w;
            acc[1][0] += a.y*b.x; acc[1][1] += a.y*b.y; acc[1][2] += a.y*b.z; acc[1][3] += a.y*b.w;
            acc[2][0] += a.z*b.x; acc[2][1] += a.z*b.y; acc[2][2] += a.z*b.z; acc[2][3] += a.z*b.w;
            acc[3][0] += a.w*b.x; acc[3][1] += a.w*b.y; acc[3][2] += a.w*b.z; acc[3][3] += a.w*b.w;
        }
        __syncthreads();
    }
#pragma unroll
    for (int i = 0; i < 4; i++)
#pragma unroll
        for (int j = 0; j < 4; j++) {
            int n = n0 + tx * 4 + j;
            C[(long)(m0 + ty * 4 + i) * ldc + n] = acc[i][j] + b1[n];
        }
}

// ---- persistent LSTM recurrence (128 CTAs x 256 thr; CTA owns 8 hidden units)
extern __shared__ float smem[];
__global__ void __launch_bounds__(256, 1)
lstm_rec(const float* __restrict__ xg, const float* __restrict__ w_hh,
         float* __restrict__ hT, float* __restrict__ h1,
         const int* __restrict__ seqlen, float* __restrict__ last) {
    float* ws  = smem;           // 16 pairs x 1024 k x 2 = 32768 floats
    float* hb0 = smem + 32768;   // 8192 floats (128 k-pairs... 128 k x 64 b)
    float* hb1 = smem + 40960;

    const int tid = threadIdx.x;
    const int kblk = blockIdx.x * 8;
    const int b = tid & 63;
    const int q = tid >> 6;

    // weight slice -> SMEM pair-interleaved: ws[(g*4+q)*2048 + 2k + u]
    for (int j = 0; j < 32; j++) {
        int g = j >> 3, uu = j & 7;
        const float* src = w_hh + (size_t)(g * H + kblk + uu) * H;
        float* dst = ws + (g * 4 + (uu >> 1)) * 2048 + (uu & 1);
        for (int k = tid; k < H; k += 256) dst[2 * k] = src[k];
    }
    __syncthreads();

    const int myseq = seqlen[b];
    float c_0 = 0.f, c_1 = 0.f;
    const int k0 = kblk + 2 * q;
    const size_t xg_b = (size_t)b * T * G4;
    const float* w0 = ws + (0 * 4 + q) * 2048;
    const float* w1 = ws + (1 * 4 + q) * 2048;
    const float* w2 = ws + (2 * 4 + q) * 2048;
    const float* w3 = ws + (3 * 4 + q) * 2048;

    for (int t = 0; t < T; t++) {
        const float* xr = xg + xg_b + (size_t)t * G4 + k0;
        float2 x_i = *(const float2*)(xr);
        float2 x_f = *(const float2*)(xr + H);
        float2 x_g = *(const float2*)(xr + 2 * H);
        float2 x_o = *(const float2*)(xr + 3 * H);
        ull acc0 = pk2(x_i.x, x_i.y), acc1 = pk2(x_f.x, x_f.y);
        ull acc2 = pk2(x_g.x, x_g.y), acc3 = pk2(x_o.x, x_o.y);

        if (t > 0) {
            const float* hsrc = hT + (size_t)(t - 1) * H * B;
            float4 r[8];
#pragma unroll
            for (int i = 0; i < 8; i++) r[i] = ((const float4*)hsrc)[tid + i * 256];
#pragma unroll
            for (int i = 0; i < 8; i++) ((float4*)hb0)[tid + i * 256] = r[i];
            __syncthreads();

            for (int ch = 0; ch < 8; ch++) {
                if (ch < 7) {
                    const float4* s = (const float4*)(hsrc + (size_t)(ch + 1) * 8192);
#pragma unroll
                    for (int i = 0; i < 8; i++) r[i] = s[tid + i * 256];
                }
                const float2* hs = (const float2*)((ch & 1) ? hb1 : hb0);
                const int kg2 = ch * 128;  // float2 base = ch*128 k /2 *... (kg*2 floats)
#pragma unroll 8
                for (int kk = 0; kk < 128; kk += 2) {
                    float2 hv = hs[(kk >> 1) * 64 + b];
                    ull hh0 = pk2(hv.x, hv.x);
                    ull hh1 = pk2(hv.y, hv.y);
                    ulonglong2 wv;
                    wv = *(const ulonglong2*)(w0 + (kg2 + kk) * 2);
                    ffma2(acc0, hh0, wv.x); ffma2(acc0, hh1, wv.y);
                    wv = *(const ulonglong2*)(w1 + (kg2 + kk) * 2);
                    ffma2(acc1, hh0, wv.x); ffma2(acc1, hh1, wv.y);
                    wv = *(const ulonglong2*)(w2 + (kg2 + kk) * 2);
                    ffma2(acc2, hh0, wv.x); ffma2(acc2, hh1, wv.y);
                    wv = *(const ulonglong2*)(w3 + (kg2 + kk) * 2);
                    ffma2(acc3, hh0, wv.x); ffma2(acc3, hh1, wv.y);
                }
                if (ch < 7) {
                    float* dst = (ch & 1) ? hb0 : hb1;
#pragma unroll
                    for (int i = 0; i < 8; i++) ((float4*)dst)[tid + i * 256] = r[i];
                    __syncthreads();
                }
            }
        }

        float2 pi = upk(acc0), pf = upk(acc1), pg = upk(acc2), po = upk(acc3);
        float i0 = sigm(pi.x), f0 = sigm(pf.x), g0 = tanhf(pg.x), o0 = sigm(po.x);
        float i1 = sigm(pi.y), f1 = sigm(pf.y), g1 = tanhf(pg.y), o1 = sigm(po.y);
        c_0 = f0 * c_0 + i0 * g0;
        c_1 = f1 * c_1 + i1 * g1;
        float h_0 = o0 * tanhf(c_0);
        float h_1 = o1 * tanhf(c_1);

        // paired store: hT[t][k0/2][b][0..1]
        *(float2*)&hT[(((size_t)t * 512 + (k0 >> 1)) * 64 + b) * 2] = make_float2(h_0, h_1);
        if (h1)
            *(float2*)&h1[((size_t)b * T + t) * H + k0] = make_float2(h_0, h_1);
        if (last && t == myseq)
            *(float2*)&last[(size_t)b * H + k0] = make_float2(h_0, h_1);

        __threadfence();
        __syncthreads();
        if (tid == 0) {
            unsigned gen = *(volatile unsigned*)&g_bar_gen;
            unsigned a = atomicAdd(&g_bar_count, 1u);
            if (a == (unsigned)(gridDim.x - 1)) {
                g_bar_count = 0;
                __threadfence();
                atomicAdd(&g_bar_gen, 1u);
            } else {
                while (*(volatile unsigned*)&g_bar_gen == gen) {}
            }
        }
        __syncthreads();
    }
}

extern "C" void kernel_launch(void* const* d_in, const int* in_sizes, int n_in,
                              void* d_out, int out_size) {
    const int*   feat  = (const int*)d_in[0];
    const float* emb   = (const float*)d_in[1];
    const float* w_ih0 = (const float*)d_in[2];
    const float* w_hh0 = (const float*)d_in[3];
    const float* b_ih0 = (const float*)d_in[4];
    const float* b_hh0 = (const float*)d_in[5];
    const float* w_ih1 = (const float*)d_in[6];
    const float* w_hh1 = (const float*)d_in[7];
    const float* b_ih1 = (const float*)d_in[8];
    const float* b_hh1 = (const float*)d_in[9];
    const float* fc_w  = (const float*)d_in[10];
    const float* fc_b  = (const float*)d_in[11];
    float* out = (float*)d_out;

    float *x0, *xg, *h1, *hT, *last; int* sl;
    cudaGetSymbolAddress((void**)&x0, g_x0);
    cudaGetSymbolAddress((void**)&xg, g_xg);
    cudaGetSymbolAddress((void**)&h1, g_h1);
    cudaGetSymbolAddress((void**)&hT, g_hT);
    cudaGetSymbolAddress((void**)&last, g_last);
    cudaGetSymbolAddress((void**)&sl, g_seqlen);

    const int REC_SMEM = 49152 * 4;  // 192 KB
    static int once = 0;
    if (!once) {
        cudaFuncSetAttribute(lstm_rec, cudaFuncAttributeMaxDynamicSharedMemorySize, REC_SMEM);
        once = 1;
    }

    seqlen_kernel<<<B, 256>>>(feat, sl);
    embed_kernel<<<B * T, E / 4>>>(feat, emb, x0);

    gemm2<<<dim3(G4 / 128, (B * T) / 128), 256>>>(x0, E, w_ih0, E, b_ih0, b_hh0, xg, G4, E);
    lstm_rec<<<128, 256, REC_SMEM>>>(xg, w_hh0, hT, h1, sl, nullptr);
    gemm2<<<dim3(G4 / 128, (B * T) / 128), 256>>>(h1, H, w_ih1, H, b_ih1, b_hh1, xg, G4, H);
    lstm_rec<<<128, 256, REC_SMEM>>>(xg, w_hh1, hT, nullptr, sl, last);
    gemm_tn<<<dim3(NC / 64, 1), 256>>>(last, H, fc_w, H, fc_b, out, NC, H);
}

// round 11
// speedup vs baseline: 1.8763x; 1.8763x over previous
#include <cuda_runtime.h>
#include <cuda_bf16.h>
#include <cstdint>
#include <math.h>

#define B   64
#define T   512
#define E   512
#define H   1024
#define G4  4096
#define NC  32000
#define VOCABM1 31999

typedef unsigned long long ull;

__device__ __align__(16) float g_x0[(size_t)B * T * E];
__device__ __align__(16) float g_xg[(size_t)B * T * G4];
__device__ __align__(16) float g_h1[(size_t)B * T * H];
__device__ __align__(16) float g_hT[(size_t)T * H * B];
__device__ __align__(16) float g_last[(size_t)B * H];
__device__ __align__(16) __nv_bfloat16 g_ahi[(size_t)B * T * H];
__device__ __align__(16) __nv_bfloat16 g_alo[(size_t)B * T * H];
__device__ __align__(16) __nv_bfloat16 g_whi[(size_t)G4 * H];
__device__ __align__(16) __nv_bfloat16 g_wlo[(size_t)G4 * H];
__device__ int g_seqlen[B];
__device__ unsigned g_bar_count, g_bar_gen;

__device__ __forceinline__ void ffma2(ull& d, ull a, ull b2) {
    asm("fma.rn.f32x2 %0, %1, %2, %0;" : "+l"(d) : "l"(a), "l"(b2));
}
__device__ __forceinline__ ull pk2(float lo, float hi) {
    ull r; asm("mov.b64 %0, {%1, %2};" : "=l"(r) : "f"(lo), "f"(hi)); return r;
}
__device__ __forceinline__ float2 upk(ull v) {
    float2 f; asm("mov.b64 {%0, %1}, %2;" : "=f"(f.x), "=f"(f.y) : "l"(v)); return f;
}
__device__ __forceinline__ float sigm(float x) { return 1.f / (1.f + expf(-x)); }
__device__ __forceinline__ uint32_t s2u(const void* p) {
    uint32_t a;
    asm("{ .reg .u64 t; cvta.to.shared.u64 t, %1; cvt.u32.u64 %0, t; }" : "=r"(a) : "l"(p));
    return a;
}

__global__ void seqlen_kernel(const int* __restrict__ feat, int* __restrict__ out) {
    int b = blockIdx.x, tid = threadIdx.x, cnt = 0;
    for (int t = tid; t < T; t += 256) cnt += (feat[b * T + t] != VOCABM1);
    __shared__ int s[256];
    s[tid] = cnt; __syncthreads();
    for (int o = 128; o > 0; o >>= 1) { if (tid < o) s[tid] += s[tid + o]; __syncthreads(); }
    if (tid == 0) out[b] = s[0] - 1;
}

__global__ void embed_kernel(const int* __restrict__ feat, const float* __restrict__ emb,
                             float* __restrict__ x0) {
    int bt = blockIdx.x;
    int f = feat[bt];
    ((float4*)(x0 + (size_t)bt * E))[threadIdx.x] =
        ((const float4*)(emb + (size_t)f * E))[threadIdx.x];
}

// Dekker split: fp32 -> bf16 hi + bf16 lo (4 elements per thread)
__global__ void split4(const float* __restrict__ src, __nv_bfloat16* __restrict__ hi,
                       __nv_bfloat16* __restrict__ lo) {
    size_t i = ((size_t)blockIdx.x * 256 + threadIdx.x) * 4;
    float4 v = *(const float4*)(src + i);
    __nv_bfloat16 h0 = __float2bfloat16(v.x), h1 = __float2bfloat16(v.y);
    __nv_bfloat16 h2 = __float2bfloat16(v.z), h3 = __float2bfloat16(v.w);
    __nv_bfloat16 l0 = __float2bfloat16(v.x - __bfloat162float(h0));
    __nv_bfloat16 l1 = __float2bfloat16(v.y - __bfloat162float(h1));
    __nv_bfloat16 l2 = __float2bfloat16(v.z - __bfloat162float(h2));
    __nv_bfloat16 l3 = __float2bfloat16(v.w - __bfloat162float(h3));
    *(__nv_bfloat162*)(hi + i)     = __nv_bfloat162(h0, h1);
    *(__nv_bfloat162*)(hi + i + 2) = __nv_bfloat162(h2, h3);
    *(__nv_bfloat162*)(lo + i)     = __nv_bfloat162(l0, l1);
    *(__nv_bfloat162*)(lo + i + 2) = __nv_bfloat162(l2, l3);
}

// ---- tensor-core TN GEMM with 3-term bf16 split ----
// C[m][n] = sum_k A[m][k]*W[n][k] + b1[n]+b2[n];  A ~ Ahi+Alo, W ~ Whi+Wlo.
// block tile 128m x 64n, 8 warps (4m x 2n), warp tile 32x32, BK=16.
__device__ __forceinline__ void mma16816(float* c, const uint32_t* a, uint32_t b0, uint32_t b1) {
    asm volatile(
        "mma.sync.aligned.m16n8k16.row.col.f32.bf16.bf16.f32 "
        "{%0,%1,%2,%3}, {%4,%5,%6,%7}, {%8,%9}, {%0,%1,%2,%3};"
        : "+f"(c[0]), "+f"(c[1]), "+f"(c[2]), "+f"(c[3])
        : "r"(a[0]), "r"(a[1]), "r"(a[2]), "r"(a[3]), "r"(b0), "r"(b1));
}
__device__ __forceinline__ void ldsm4(uint32_t* r, uint32_t addr) {
    asm volatile("ldmatrix.sync.aligned.m8n8.x4.shared.b16 {%0,%1,%2,%3}, [%4];"
                 : "=r"(r[0]), "=r"(r[1]), "=r"(r[2]), "=r"(r[3]) : "r"(addr));
}

__global__ void __launch_bounds__(256)
gemm_mma(const __nv_bfloat16* __restrict__ Ahi, const __nv_bfloat16* __restrict__ Alo,
         const __nv_bfloat16* __restrict__ Whi, const __nv_bfloat16* __restrict__ Wlo,
         const float* __restrict__ b1, const float* __restrict__ b2,
         float* __restrict__ C, int ldc, int K) {
    __shared__ __nv_bfloat16 sAh[128 * 16], sAl[128 * 16];
    __shared__ __nv_bfloat16 sBh[64 * 16],  sBl[64 * 16];

    const int tid = threadIdx.x, lane = tid & 31, wid = tid >> 5;
    const int m0 = blockIdx.y * 128, n0 = blockIdx.x * 64;
    const int wm = (wid & 3) * 32, wn = (wid >> 2) * 32;

    // loaders
    const int lrow = tid >> 1, lk = (tid & 1) * 8;
    const __nv_bfloat16* Aph = Ahi + (size_t)(m0 + lrow) * K + lk;
    const __nv_bfloat16* Apl = Alo + (size_t)(m0 + lrow) * K + lk;
    const int bsel = tid >> 7, brow = (tid >> 1) & 63, bk = (tid & 1) * 8;
    const __nv_bfloat16* Bp = (bsel ? Wlo : Whi) + (size_t)(n0 + brow) * K + bk;
    __nv_bfloat16* sB = bsel ? sBl : sBh;

    // ldmatrix lane addresses (byte offsets; smem rows are 32B)
    const uint32_t aOff = (uint32_t)((wm + ((lane >> 3) & 1) * 8 + (lane & 7)) * 32 +
                                     (lane >> 4) * 16);
    const uint32_t bOff = (uint32_t)((wn + (lane >> 4) * 8 + (lane & 7)) * 32 +
                                     ((lane >> 3) & 1) * 16);
    const uint32_t uAh = s2u(sAh), uAl = s2u(sAl), uBh = s2u(sBh), uBl = s2u(sBl);

    float acc[2][4][4];
#pragma unroll
    for (int i = 0; i < 2; i++)
#pragma unroll
        for (int j = 0; j < 4; j++)
#pragma unroll
            for (int l = 0; l < 4; l++) acc[i][j][l] = 0.f;

    for (int kt = 0; kt < K; kt += 16) {
        *(uint4*)&sAh[lrow * 16 + lk] = *(const uint4*)(Aph + kt);
        *(uint4*)&sAl[lrow * 16 + lk] = *(const uint4*)(Apl + kt);
        *(uint4*)&sB[brow * 16 + bk]  = *(const uint4*)(Bp + kt);
        __syncthreads();

        uint32_t ah[2][4], al[2][4], bh[2][4], bl[2][4];
#pragma unroll
        for (int mt = 0; mt < 2; mt++) {
            ldsm4(ah[mt], uAh + aOff + mt * 512);
            ldsm4(al[mt], uAl + aOff + mt * 512);
        }
#pragma unroll
        for (int g = 0; g < 2; g++) {
            ldsm4(bh[g], uBh + bOff + g * 512);
            ldsm4(bl[g], uBl + bOff + g * 512);
        }
#pragma unroll
        for (int mt = 0; mt < 2; mt++)
#pragma unroll
            for (int nt = 0; nt < 4; nt++) {
                uint32_t h0 = bh[nt >> 1][(nt & 1) * 2], h1 = bh[nt >> 1][(nt & 1) * 2 + 1];
                uint32_t l0 = bl[nt >> 1][(nt & 1) * 2], l1 = bl[nt >> 1][(nt & 1) * 2 + 1];
                mma16816(acc[mt][nt], ah[mt], h0, h1);   // hi*hi
                mma16816(acc[mt][nt], ah[mt], l0, l1);   // hi*lo
                mma16816(acc[mt][nt], al[mt], h0, h1);   // lo*hi
            }
        __syncthreads();
    }

    const int r = lane >> 2, cn = (lane & 3) * 2;
#pragma unroll
    for (int mt = 0; mt < 2; mt++)
#pragma unroll
        for (int nt = 0; nt < 4; nt++) {
            int n = n0 + wn + nt * 8 + cn;
            float bb0 = b1[n] + b2[n], bb1 = b1[n + 1] + b2[n + 1];
            int m = m0 + wm + mt * 16 + r;
            float* c = acc[mt][nt];
            *(float2*)&C[(size_t)m * ldc + n]       = make_float2(c[0] + bb0, c[1] + bb1);
            *(float2*)&C[(size_t)(m + 8) * ldc + n] = make_float2(c[2] + bb0, c[3] + bb1);
        }
}

// ---- scalar TN GEMM for FC head ----
__global__ void gemm_tn(const float* __restrict__ A, long lda,
                        const float* __restrict__ W, int ldw,
                        const float* __restrict__ b1,
                        float* __restrict__ C, int ldc, int K) {
    __shared__ float As[16][68];
    __shared__ float Bs[16][68];
    const int tid = threadIdx.x;
    const int m0 = blockIdx.y * 64, n0 = blockIdx.x * 64;
    const float* Ap = A + (long)m0 * lda;
    const float* Wp = W + (long)n0 * ldw;
    const int lr = tid >> 2, lk = (tid & 3) * 4, ty = tid >> 4, tx = tid & 15;
    float acc[4][4];
#pragma unroll
    for (int i = 0; i < 4; i++)
#pragma unroll
        for (int j = 0; j < 4; j++) acc[i][j] = 0.f;
    for (int kt = 0; kt < K; kt += 16) {
        float4 a4 = *(const float4*)(Ap + (long)lr * lda + kt + lk);
        float4 w4 = *(const float4*)(Wp + (long)lr * ldw + kt + lk);
        As[lk + 0][lr] = a4.x; As[lk + 1][lr] = a4.y;
        As[lk + 2][lr] = a4.z; As[lk + 3][lr] = a4.w;
        Bs[lk + 0][lr] = w4.x; Bs[lk + 1][lr] = w4.y;
        Bs[lk + 2][lr] = w4.z; Bs[lk + 3][lr] = w4.w;
        __syncthreads();
#pragma unroll
        for (int kk = 0; kk < 16; kk++) {
            float4 a = *(const float4*)&As[kk][ty * 4];
            float4 b = *(const float4*)&Bs[kk][tx * 4];
            acc[0][0] += a.x*b.x; acc[0][1] += a.x*b.y; acc[0][2] += a.x*b.z; acc[0][3] += a.x*b.w;
            acc[1][0] += a.y*b.x; acc[1][1] += a.y*b.y; acc[1][2] += a.y*b.z; acc[1][3] += a.y*b.w;
            acc[2][0] += a.z*b.x; acc[2][1] += a.z*b.y; acc[2][2] += a.z*b.z; acc[2][3] += a.z*b.w;
            acc[3][0] += a.w*b.x; acc[3][1] += a.w*b.y; acc[3][2] += a.w*b.z; acc[3][3] += a.w*b.w;
        }
        __syncthreads();
    }
#pragma unroll
    for (int i = 0; i < 4; i++)
#pragma unroll
        for (int j = 0; j < 4; j++) {
            int n = n0 + tx * 4 + j;
            C[(long)(m0 + ty * 4 + i) * ldc + n] = acc[i][j] + b1[n];
        }
}

// ---- persistent LSTM recurrence (exact R2 version, measured-good) ----
extern __shared__ float smem[];
__global__ void __launch_bounds__(256, 1)
lstm_rec(const float* __restrict__ xg, const float* __restrict__ w_hh,
         float* __restrict__ hT, float* __restrict__ h1,
         const int* __restrict__ seqlen, float* __restrict__ last) {
    float* ws = smem;
    float* hb0 = smem + 32768;
    float* hb1 = smem + 40960;

    const int tid = threadIdx.x;
    const int kblk = blockIdx.x * 8;
    const int b = tid & 63;
    const int q = tid >> 6;

    for (int j = 0; j < 32; j++) {
        int n = ((j >> 3) << 10) + kblk + (j & 7);
        const float* src = w_hh + (size_t)n * H;
        float* dst = ws + (size_t)(j >> 1) * 2048 + (j & 1);
        for (int k = tid; k < H; k += 256) dst[k * 2] = src[k];
    }
    __syncthreads();

    const int myseq = seqlen[b];
    float c_0 = 0.f, c_1 = 0.f;
    const size_t xg_b = (size_t)b * T * G4;
    const int k0 = kblk + 2 * q;

    for (int t = 0; t < T; t++) {
        const float* xr = xg + xg_b + (size_t)t * G4 + k0;
        float2 x_i = *(const float2*)(xr);
        float2 x_f = *(const float2*)(xr + H);
        float2 x_g = *(const float2*)(xr + 2 * H);
        float2 x_o = *(const float2*)(xr + 3 * H);

        ull acc0 = pk2(x_i.x, x_i.y), acc1 = pk2(x_f.x, x_f.y);
        ull acc2 = pk2(x_g.x, x_g.y), acc3 = pk2(x_o.x, x_o.y);

        if (t > 0) {
            const float* hsrc = hT + (size_t)(t - 1) * H * B;
            float4 r[8];
#pragma unroll
            for (int i = 0; i < 8; i++) r[i] = ((const float4*)hsrc)[tid + i * 256];
#pragma unroll
            for (int i = 0; i < 8; i++) ((float4*)hb0)[tid + i * 256] = r[i];
            __syncthreads();

            for (int ch = 0; ch < 8; ch++) {
                if (ch < 7) {
                    const float4* s = (const float4*)(hsrc + (size_t)(ch + 1) * 128 * B);
#pragma unroll
                    for (int i = 0; i < 8; i++) r[i] = s[tid + i * 256];
                }
                const float* hs = (ch & 1) ? hb1 : hb0;
                const int kg = ch * 128;
                const float* w0 = ws + (size_t)((0 * 4 + q) * 1024 + kg) * 2;
                const float* w1 = ws + (size_t)((1 * 4 + q) * 1024 + kg) * 2;
                const float* w2 = ws + (size_t)((2 * 4 + q) * 1024 + kg) * 2;
                const float* w3 = ws + (size_t)((3 * 4 + q) * 1024 + kg) * 2;
#pragma unroll 8
                for (int kk = 0; kk < 128; kk += 2) {
                    float hv0 = hs[kk * 64 + b];
                    float hv1 = hs[(kk + 1) * 64 + b];
                    ull hh0 = pk2(hv0, hv0);
                    ull hh1 = pk2(hv1, hv1);
                    float4 wv;
                    wv = *(const float4*)(w0 + kk * 2);
                    ffma2(acc0, hh0, pk2(wv.x, wv.y));
                    ffma2(acc0, hh1, pk2(wv.z, wv.w));
                    wv = *(const float4*)(w1 + kk * 2);
                    ffma2(acc1, hh0, pk2(wv.x, wv.y));
                    ffma2(acc1, hh1, pk2(wv.z, wv.w));
                    wv = *(const float4*)(w2 + kk * 2);
                    ffma2(acc2, hh0, pk2(wv.x, wv.y));
                    ffma2(acc2, hh1, pk2(wv.z, wv.w));
                    wv = *(const float4*)(w3 + kk * 2);
                    ffma2(acc3, hh0, pk2(wv.x, wv.y));
                    ffma2(acc3, hh1, pk2(wv.z, wv.w));
                }
                if (ch < 7) {
                    float* dst = (ch & 1) ? hb0 : hb1;
#pragma unroll
                    for (int i = 0; i < 8; i++) ((float4*)dst)[tid + i * 256] = r[i];
                    __syncthreads();
                }
            }
        }

        float2 pi = upk(acc0), pf = upk(acc1), pg = upk(acc2), po = upk(acc3);
        float i0 = sigm(pi.x), f0 = sigm(pf.x), g0 = tanhf(pg.x), o0 = sigm(po.x);
        float i1 = sigm(pi.y), f1 = sigm(pf.y), g1 = tanhf(pg.y), o1 = sigm(po.y);
        c_0 = f0 * c_0 + i0 * g0;
        c_1 = f1 * c_1 + i1 * g1;
        float h_0 = o0 * tanhf(c_0);
        float h_1 = o1 * tanhf(c_1);

        hT[((size_t)t * H + k0) * B + b]     = h_0;
        hT[((size_t)t * H + k0 + 1) * B + b] = h_1;
        if (h1)
            *(float2*)&h1[((size_t)b * T + t) * H + k0] = make_float2(h_0, h_1);
        if (last && t == myseq)
            *(float2*)&last[(size_t)b * H + k0] = make_float2(h_0, h_1);

        __threadfence();
        __syncthreads();
        if (tid == 0) {
            unsigned gen = *(volatile unsigned*)&g_bar_gen;
            unsigned a = atomicAdd(&g_bar_count, 1u);
            if (a == (unsigned)(gridDim.x - 1)) {
                g_bar_count = 0;
                __threadfence();
                atomicAdd(&g_bar_gen, 1u);
            } else {
                while (*(volatile unsigned*)&g_bar_gen == gen) {}
            }
        }
        __syncthreads();
    }
}

extern "C" void kernel_launch(void* const* d_in, const int* in_sizes, int n_in,
                              void* d_out, int out_size) {
    const int*   feat  = (const int*)d_in[0];
    const float* emb   = (const float*)d_in[1];
    const float* w_ih0 = (const float*)d_in[2];
    const float* w_hh0 = (const float*)d_in[3];
    const float* b_ih0 = (const float*)d_in[4];
    const float* b_hh0 = (const float*)d_in[5];
    const float* w_ih1 = (const float*)d_in[6];
    const float* w_hh1 = (const float*)d_in[7];
    const float* b_ih1 = (const float*)d_in[8];
    const float* b_hh1 = (const float*)d_in[9];
    const float* fc_w  = (const float*)d_in[10];
    const float* fc_b  = (const float*)d_in[11];
    float* out = (float*)d_out;

    float *x0, *xg, *h1, *hT, *last; int* sl;
    __nv_bfloat16 *ahi, *alo, *whi, *wlo;
    cudaGetSymbolAddress((void**)&x0, g_x0);
    cudaGetSymbolAddress((void**)&xg, g_xg);
    cudaGetSymbolAddress((void**)&h1, g_h1);
    cudaGetSymbolAddress((void**)&hT, g_hT);
    cudaGetSymbolAddress((void**)&last, g_last);
    cudaGetSymbolAddress((void**)&sl, g_seqlen);
    cudaGetSymbolAddress((void**)&ahi, g_ahi);
    cudaGetSymbolAddress((void**)&alo, g_alo);
    cudaGetSymbolAddress((void**)&whi, g_whi);
    cudaGetSymbolAddress((void**)&wlo, g_wlo);

    const int REC_SMEM = 49152 * 4;  // 192 KB
    static int once = 0;
    if (!once) {
        cudaFuncSetAttribute(lstm_rec, cudaFuncAttributeMaxDynamicSharedMemorySize, REC_SMEM);
        once = 1;
    }

    seqlen_kernel<<<B, 256>>>(feat, sl);
    embed_kernel<<<B * T, E / 4>>>(feat, emb, x0);

    // ---- layer 0 projection on tensor cores ----
    split4<<<(B * T * E) / 1024, 256>>>(x0, ahi, alo);
    split4<<<(G4 * E) / 1024, 256>>>(w_ih0, whi, wlo);
    gemm_mma<<<dim3(G4 / 64, (B * T) / 128), 256>>>(ahi, alo, whi, wlo,
                                                    b_ih0, b_hh0, xg, G4, E);
    lstm_rec<<<128, 256, REC_SMEM>>>(xg, w_hh0, hT, h1, sl, nullptr);

    // ---- layer 1 projection on tensor cores ----
    split4<<<(B * T * H) / 1024, 256>>>(h1, ahi, alo);
    split4<<<(G4 * H) / 1024, 256>>>(w_ih1, whi, wlo);
    gemm_mma<<<dim3(G4 / 64, (B * T) / 128), 256>>>(ahi, alo, whi, wlo,
                                                    b_ih1, b_hh1, xg, G4, H);
    lstm_rec<<<128, 256, REC_SMEM>>>(xg, w_hh1, hT, nullptr, sl, last);

    gemm_tn<<<dim3(NC / 64, 1), 256>>>(last, H, fc_w, H, fc_b, out, NC, H);
}

// round 12
// speedup vs baseline: 2.8517x; 1.5198x over previous
#include <cuda_runtime.h>
#include <cuda_bf16.h>
#include <cstdint>
#include <math.h>

#define B   64
#define T   512
#define E   512
#define H   1024
#define G4  4096
#define NC  32000
#define VOCABM1 31999

typedef unsigned long long ull;

__device__ __align__(16) float g_x0[(size_t)B * T * E];
__device__ __align__(16) float g_xg[(size_t)B * T * G4];
__device__ __align__(16) float g_h1[(size_t)B * T * H];
__device__ __align__(16) float g_last[(size_t)B * H];
__device__ __align__(16) __nv_bfloat16 g_ahi[(size_t)B * T * H];
__device__ __align__(16) __nv_bfloat16 g_alo[(size_t)B * T * H];
__device__ __align__(16) __nv_bfloat16 g_whi[(size_t)G4 * H];
__device__ __align__(16) __nv_bfloat16 g_wlo[(size_t)G4 * H];
// h ping-pong, packed mma-tile layout: [slot][kt 64][b 64][kk 16]
__device__ __align__(16) __nv_bfloat16 g_hH[2 * 64 * 64 * 16];
__device__ __align__(16) __nv_bfloat16 g_hL[2 * 64 * 64 * 16];
__device__ int g_seqlen[B];
__device__ unsigned g_bar_count, g_bar_gen;

__device__ __forceinline__ float sigm(float x) { return 1.f / (1.f + expf(-x)); }
__device__ __forceinline__ uint32_t s2u(const void* p) {
    uint32_t a;
    asm("{ .reg .u64 t; cvta.to.shared.u64 t, %1; cvt.u32.u64 %0, t; }" : "=r"(a) : "l"(p));
    return a;
}
__device__ __forceinline__ void mma16816(float* c, const uint32_t* a, uint32_t b0, uint32_t b1) {
    asm volatile(
        "mma.sync.aligned.m16n8k16.row.col.f32.bf16.bf16.f32 "
        "{%0,%1,%2,%3}, {%4,%5,%6,%7}, {%8,%9}, {%0,%1,%2,%3};"
        : "+f"(c[0]), "+f"(c[1]), "+f"(c[2]), "+f"(c[3])
        : "r"(a[0]), "r"(a[1]), "r"(a[2]), "r"(a[3]), "r"(b0), "r"(b1));
}
__device__ __forceinline__ void ldsm4(uint32_t* r, uint32_t addr) {
    asm volatile("ldmatrix.sync.aligned.m8n8.x4.shared.b16 {%0,%1,%2,%3}, [%4];"
                 : "=r"(r[0]), "=r"(r[1]), "=r"(r[2]), "=r"(r[3]) : "r"(addr));
}

__global__ void seqlen_kernel(const int* __restrict__ feat, int* __restrict__ out) {
    int b = blockIdx.x, tid = threadIdx.x, cnt = 0;
    for (int t = tid; t < T; t += 256) cnt += (feat[b * T + t] != VOCABM1);
    __shared__ int s[256];
    s[tid] = cnt; __syncthreads();
    for (int o = 128; o > 0; o >>= 1) { if (tid < o) s[tid] += s[tid + o]; __syncthreads(); }
    if (tid == 0) out[b] = s[0] - 1;
}

__global__ void embed_kernel(const int* __restrict__ feat, const float* __restrict__ emb,
                             float* __restrict__ x0) {
    int bt = blockIdx.x;
    int f = feat[bt];
    ((float4*)(x0 + (size_t)bt * E))[threadIdx.x] =
        ((const float4*)(emb + (size_t)f * E))[threadIdx.x];
}

__global__ void split4(const float* __restrict__ src, __nv_bfloat16* __restrict__ hi,
                       __nv_bfloat16* __restrict__ lo) {
    size_t i = ((size_t)blockIdx.x * 256 + threadIdx.x) * 4;
    float4 v = *(const float4*)(src + i);
    __nv_bfloat16 h0 = __float2bfloat16(v.x), h1 = __float2bfloat16(v.y);
    __nv_bfloat16 h2 = __float2bfloat16(v.z), h3 = __float2bfloat16(v.w);
    __nv_bfloat16 l0 = __float2bfloat16(v.x - __bfloat162float(h0));
    __nv_bfloat16 l1 = __float2bfloat16(v.y - __bfloat162float(h1));
    __nv_bfloat16 l2 = __float2bfloat16(v.z - __bfloat162float(h2));
    __nv_bfloat16 l3 = __float2bfloat16(v.w - __bfloat162float(h3));
    *(__nv_bfloat162*)(hi + i)     = __nv_bfloat162(h0, h1);
    *(__nv_bfloat162*)(hi + i + 2) = __nv_bfloat162(h2, h3);
    *(__nv_bfloat162*)(lo + i)     = __nv_bfloat162(l0, l1);
    *(__nv_bfloat162*)(lo + i + 2) = __nv_bfloat162(l2, l3);
}

// ---- tensor-core TN GEMM with 3-term bf16 split (R6-verified) ----
__global__ void __launch_bounds__(256)
gemm_mma(const __nv_bfloat16* __restrict__ Ahi, const __nv_bfloat16* __restrict__ Alo,
         const __nv_bfloat16* __restrict__ Whi, const __nv_bfloat16* __restrict__ Wlo,
         const float* __restrict__ b1, const float* __restrict__ b2,
         float* __restrict__ C, int ldc, int K) {
    __shared__ __nv_bfloat16 sAh[128 * 16], sAl[128 * 16];
    __shared__ __nv_bfloat16 sBh[64 * 16],  sBl[64 * 16];

    const int tid = threadIdx.x, lane = tid & 31, wid = tid >> 5;
    const int m0 = blockIdx.y * 128, n0 = blockIdx.x * 64;
    const int wm = (wid & 3) * 32, wn = (wid >> 2) * 32;

    const int lrow = tid >> 1, lk = (tid & 1) * 8;
    const __nv_bfloat16* Aph = Ahi + (size_t)(m0 + lrow) * K + lk;
    const __nv_bfloat16* Apl = Alo + (size_t)(m0 + lrow) * K + lk;
    const int bsel = tid >> 7, brow = (tid >> 1) & 63, bk = (tid & 1) * 8;
    const __nv_bfloat16* Bp = (bsel ? Wlo : Whi) + (size_t)(n0 + brow) * K + bk;
    __nv_bfloat16* sB = bsel ? sBl : sBh;

    const uint32_t aOff = (uint32_t)((wm + ((lane >> 3) & 1) * 8 + (lane & 7)) * 32 +
                                     (lane >> 4) * 16);
    const uint32_t bOff = (uint32_t)((wn + (lane >> 4) * 8 + (lane & 7)) * 32 +
                                     ((lane >> 3) & 1) * 16);
    const uint32_t uAh = s2u(sAh), uAl = s2u(sAl), uBh = s2u(sBh), uBl = s2u(sBl);

    float acc[2][4][4];
#pragma unroll
    for (int i = 0; i < 2; i++)
#pragma unroll
        for (int j = 0; j < 4; j++)
#pragma unroll
            for (int l = 0; l < 4; l++) acc[i][j][l] = 0.f;

    for (int kt = 0; kt < K; kt += 16) {
        *(uint4*)&sAh[lrow * 16 + lk] = *(const uint4*)(Aph + kt);
        *(uint4*)&sAl[lrow * 16 + lk] = *(const uint4*)(Apl + kt);
        *(uint4*)&sB[brow * 16 + bk]  = *(const uint4*)(Bp + kt);
        __syncthreads();

        uint32_t ah[2][4], al[2][4], bh[2][4], bl[2][4];
#pragma unroll
        for (int mt = 0; mt < 2; mt++) {
            ldsm4(ah[mt], uAh + aOff + mt * 512);
            ldsm4(al[mt], uAl + aOff + mt * 512);
        }
#pragma unroll
        for (int g = 0; g < 2; g++) {
            ldsm4(bh[g], uBh + bOff + g * 512);
            ldsm4(bl[g], uBl + bOff + g * 512);
        }
#pragma unroll
        for (int mt = 0; mt < 2; mt++)
#pragma unroll
            for (int nt = 0; nt < 4; nt++) {
                uint32_t h0 = bh[nt >> 1][(nt & 1) * 2], h1 = bh[nt >> 1][(nt & 1) * 2 + 1];
                uint32_t l0 = bl[nt >> 1][(nt & 1) * 2], l1 = bl[nt >> 1][(nt & 1) * 2 + 1];
                mma16816(acc[mt][nt], ah[mt], h0, h1);
                mma16816(acc[mt][nt], ah[mt], l0, l1);
                mma16816(acc[mt][nt], al[mt], h0, h1);
            }
        __syncthreads();
    }

    const int r = lane >> 2, cn = (lane & 3) * 2;
#pragma unroll
    for (int mt = 0; mt < 2; mt++)
#pragma unroll
        for (int nt = 0; nt < 4; nt++) {
            int n = n0 + wn + nt * 8 + cn;
            float bb0 = b1[n] + b2[n], bb1 = b1[n + 1] + b2[n + 1];
            int m = m0 + wm + mt * 16 + r;
            float* c = acc[mt][nt];
            *(float2*)&C[(size_t)m * ldc + n]       = make_float2(c[0] + bb0, c[1] + bb1);
            *(float2*)&C[(size_t)(m + 8) * ldc + n] = make_float2(c[2] + bb0, c[3] + bb1);
        }
}

// ---- scalar TN GEMM for FC head ----
__global__ void gemm_tn(const float* __restrict__ A, long lda,
                        const float* __restrict__ W, int ldw,
                        const float* __restrict__ b1,
                        float* __restrict__ C, int ldc, int K) {
    __shared__ float As[16][68];
    __shared__ float Bs[16][68];
    const int tid = threadIdx.x;
    const int m0 = blockIdx.y * 64, n0 = blockIdx.x * 64;
    const float* Ap = A + (long)m0 * lda;
    const float* Wp = W + (long)n0 * ldw;
    const int lr = tid >> 2, lk = (tid & 3) * 4, ty = tid >> 4, tx = tid & 15;
    float acc[4][4];
#pragma unroll
    for (int i = 0; i < 4; i++)
#pragma unroll
        for (int j = 0; j < 4; j++) acc[i][j] = 0.f;
    for (int kt = 0; kt < K; kt += 16) {
        float4 a4 = *(const float4*)(Ap + (long)lr * lda + kt + lk);
        float4 w4 = *(const float4*)(Wp + (long)lr * ldw + kt + lk);
        As[lk + 0][lr] = a4.x; As[lk + 1][lr] = a4.y;
        As[lk + 2][lr] = a4.z; As[lk + 3][lr] = a4.w;
        Bs[lk + 0][lr] = w4.x; Bs[lk + 1][lr] = w4.y;
        Bs[lk + 2][lr] = w4.z; Bs[lk + 3][lr] = w4.w;
        __syncthreads();
#pragma unroll
        for (int kk = 0; kk < 16; kk++) {
            float4 a = *(const float4*)&As[kk][ty * 4];
            float4 b = *(const float4*)&Bs[kk][tx * 4];
            acc[0][0] += a.x*b.x; acc[0][1] += a.x*b.y; acc[0][2] += a.x*b.z; acc[0][3] += a.x*b.w;
            acc[1][0] += a.y*b.x; acc[1][1] += a.y*b.y; acc[1][2] += a.y*b.z; acc[1][3] += a.y*b.w;
            acc[2][0] += a.z*b.x; acc[2][1] += a.z*b.y; acc[2][2] += a.z*b.z; acc[2][3] += a.z*b.w;
            acc[3][0] += a.w*b.x; acc[3][1] += a.w*b.y; acc[3][2] += a.w*b.z; acc[3][3] += a.w*b.w;
        }
        __syncthreads();
    }
#pragma unroll
    for (int i = 0; i < 4; i++)
#pragma unroll
        for (int j = 0; j < 4; j++) {
            int n = n0 + tx * 4 + j;
            C[(long)(m0 + ty * 4 + i) * ldc + n] = acc[i][j] + b1[n];
        }
}

// ---- persistent tensor-core LSTM recurrence ----
// 128 CTAs x 256 thr (8 warps). CTA c owns hidden units [8c,8c+8) across all 4 gates
// (32 w_hh rows), pre-split bf16 hi/lo, tiled in SMEM. Per step: 64x32 = h @ slice^T
// via mma (3-term split), gate mix in SMEM, cell fp32, h -> packed bf16 ping-pong
// global, ONE grid barrier.
// SMEM: sW [64kt][2term][32n][16k] = 128KB | sA [2buf][2term][8tile][64b][16k] = 64KB
//     | gbuf [4g][8u][64b] f32 = 8KB.  Total 204800 B.
extern __shared__ char rsm[];
__global__ void __launch_bounds__(256, 1)
lstm_rec(const float* __restrict__ xg, const float* __restrict__ w_hh,
         float* __restrict__ h1, const int* __restrict__ seqlen,
         float* __restrict__ last) {
    __nv_bfloat16* sW = (__nv_bfloat16*)rsm;              // 131072 B
    __nv_bfloat16* sA = (__nv_bfloat16*)(rsm + 131072);   // 65536 B
    float* gbuf = (float*)(rsm + 196608);                 // 8192 B

    const int tid = threadIdx.x, lane = tid & 31, wid = tid >> 5;
    const int cta = blockIdx.x;
    const int mt = wid & 3, nh = wid >> 2;

    // ---- stage weight slice: rows n_local = g*8+u -> w_hh[g*1024 + cta*8 + u][k]
    for (int idx = tid; idx < 32 * 1024; idx += 256) {
        int nl = idx >> 10, k = idx & 1023;
        int g = nl >> 3, u = nl & 7, kt = k >> 4, kk = k & 15;
        float w = w_hh[(size_t)(g * 1024 + cta * 8 + u) * H + k];
        __nv_bfloat16 hi = __float2bfloat16(w);
        __nv_bfloat16 lo = __float2bfloat16(w - __bfloat162float(hi));
        sW[(kt * 2 + 0) * 512 + nl * 16 + kk] = hi;
        sW[(kt * 2 + 1) * 512 + nl * 16 + kk] = lo;
    }
    __syncthreads();

    const uint32_t uW = s2u(sW), uA = s2u(sA);
    const uint32_t aOff = (uint32_t)((mt * 16 + ((lane >> 3) & 1) * 8 + (lane & 7)) * 32 +
                                     (lane >> 4) * 16);
    const uint32_t bOff = (uint32_t)((nh * 16 + (lane >> 4) * 8 + (lane & 7)) * 32 +
                                     ((lane >> 3) & 1) * 16);

    const int cb = tid & 63, kp = tid >> 6, u0 = 2 * kp;
    const int myseq = seqlen[cb];
    const int khid = cta * 8 + u0;                 // hidden unit pair base
    const int kt_h = khid >> 4, kk_h = khid & 15;  // packed-slot coords
    float c_0 = 0.f, c_1 = 0.f;

    const int r = lane >> 2, cn = (lane & 3) * 2;

    for (int t = 0; t < T; t++) {
        float acc[2][4];
#pragma unroll
        for (int i = 0; i < 2; i++)
#pragma unroll
            for (int j = 0; j < 4; j++) acc[i][j] = 0.f;

        if (t > 0) {
            const int sp = (t - 1) & 1;
            const uint4* gh = (const uint4*)(g_hH + sp * 65536);
            const uint4* gl = (const uint4*)(g_hL + sp * 65536);
            uint4 rg[8];
            // prologue: chunk 0 -> buf 0
#pragma unroll
            for (int i = 0; i < 4; i++) {
                rg[i] = gh[tid + i * 256];
                rg[4 + i] = gl[tid + i * 256];
            }
#pragma unroll
            for (int i = 0; i < 4; i++) {
                ((uint4*)sA)[tid + i * 256] = rg[i];            // term hi
                ((uint4*)sA)[1024 + tid + i * 256] = rg[4 + i]; // term lo
            }
            __syncthreads();

            for (int ch = 0; ch < 8; ch++) {
                if (ch < 7) {
#pragma unroll
                    for (int i = 0; i < 4; i++) {
                        rg[i] = gh[(ch + 1) * 1024 + tid + i * 256];
                        rg[4 + i] = gl[(ch + 1) * 1024 + tid + i * 256];
                    }
                }
                const uint32_t abase = uA + (ch & 1) * 32768;
#pragma unroll
                for (int j = 0; j < 8; j++) {
                    const int kt = ch * 8 + j;
                    uint32_t ah[4], al[4], bh[4], bl[4];
                    ldsm4(ah, abase + j * 2048 + aOff);
                    ldsm4(al, abase + 16384 + j * 2048 + aOff);
                    ldsm4(bh, uW + kt * 2048 + bOff);
                    ldsm4(bl, uW + kt * 2048 + 1024 + bOff);
                    mma16816(acc[0], ah, bh[0], bh[1]);
                    mma16816(acc[0], ah, bl[0], bl[1]);
                    mma16816(acc[0], al, bh[0], bh[1]);
                    mma16816(acc[1], ah, bh[2], bh[3]);
                    mma16816(acc[1], ah, bl[2], bl[3]);
                    mma16816(acc[1], al, bh[2], bh[3]);
                }
                if (ch < 7) {
                    const int ob = ((ch + 1) & 1) * 2048;
#pragma unroll
                    for (int i = 0; i < 4; i++) {
                        ((uint4*)sA)[ob + tid + i * 256] = rg[i];
                        ((uint4*)sA)[ob + 1024 + tid + i * 256] = rg[4 + i];
                    }
                    __syncthreads();
                }
            }
        }

        // ---- gate mix through SMEM: gbuf[(gate*8+u)*64 + b]
#pragma unroll
        for (int ng = 0; ng < 2; ng++) {
            const int gate = nh * 2 + ng;
            gbuf[(gate * 8 + cn) * 64 + mt * 16 + r]     = acc[ng][0];
            gbuf[(gate * 8 + cn + 1) * 64 + mt * 16 + r] = acc[ng][1];
            gbuf[(gate * 8 + cn) * 64 + mt * 16 + r + 8]     = acc[ng][2];
            gbuf[(gate * 8 + cn + 1) * 64 + mt * 16 + r + 8] = acc[ng][3];
        }
        __syncthreads();

        // ---- cell: thread -> (batch cb, units khid, khid+1)
        {
            const float* xr = xg + ((size_t)cb * T + t) * G4 + khid;
            float2 xi = *(const float2*)(xr);
            float2 xf = *(const float2*)(xr + H);
            float2 xgg = *(const float2*)(xr + 2 * H);
            float2 xo = *(const float2*)(xr + 3 * H);
            float pi0 = gbuf[(0 * 8 + u0) * 64 + cb] + xi.x;
            float pi1 = gbuf[(0 * 8 + u0 + 1) * 64 + cb] + xi.y;
            float pf0 = gbuf[(1 * 8 + u0) * 64 + cb] + xf.x;
            float pf1 = gbuf[(1 * 8 + u0 + 1) * 64 + cb] + xf.y;
            float pg0 = gbuf[(2 * 8 + u0) * 64 + cb] + xgg.x;
            float pg1 = gbuf[(2 * 8 + u0 + 1) * 64 + cb] + xgg.y;
            float po0 = gbuf[(3 * 8 + u0) * 64 + cb] + xo.x;
            float po1 = gbuf[(3 * 8 + u0 + 1) * 64 + cb] + xo.y;

            float i0 = sigm(pi0), f0 = sigm(pf0), gg0 = tanhf(pg0), o0 = sigm(po0);
            float i1 = sigm(pi1), f1 = sigm(pf1), gg1 = tanhf(pg1), o1 = sigm(po1);
            c_0 = f0 * c_0 + i0 * gg0;
            c_1 = f1 * c_1 + i1 * gg1;
            float h_0 = o0 * tanhf(c_0);
            float h_1 = o1 * tanhf(c_1);

            // packed bf16 hi/lo, slot t&1, layout [kt][b][kk]
            __nv_bfloat16 hh0 = __float2bfloat16(h_0);
            __nv_bfloat16 hh1 = __float2bfloat16(h_1);
            __nv_bfloat16 hl0 = __float2bfloat16(h_0 - __bfloat162float(hh0));
            __nv_bfloat16 hl1 = __float2bfloat16(h_1 - __bfloat162float(hh1));
            const size_t po = (size_t)((t & 1) * 4096 + kt_h * 64 + cb) * 16 + kk_h;
            *(__nv_bfloat162*)(g_hH + po) = __nv_bfloat162(hh0, hh1);
            *(__nv_bfloat162*)(g_hL + po) = __nv_bfloat162(hl0, hl1);

            if (h1)
                *(float2*)&h1[((size_t)cb * T + t) * H + khid] = make_float2(h_0, h_1);
            if (last && t == myseq)
                *(float2*)&last[(size_t)cb * H + khid] = make_float2(h_0, h_1);
        }

        // ---- grid barrier ----
        __threadfence();
        __syncthreads();
        if (tid == 0) {
            unsigned gen = *(volatile unsigned*)&g_bar_gen;
            unsigned a = atomicAdd(&g_bar_count, 1u);
            if (a == (unsigned)(gridDim.x - 1)) {
                g_bar_count = 0;
                __threadfence();
                atomicAdd(&g_bar_gen, 1u);
            } else {
                while (*(volatile unsigned*)&g_bar_gen == gen) {}
            }
        }
        __syncthreads();
    }
}

extern "C" void kernel_launch(void* const* d_in, const int* in_sizes, int n_in,
                              void* d_out, int out_size) {
    const int*   feat  = (const int*)d_in[0];
    const float* emb   = (const float*)d_in[1];
    const float* w_ih0 = (const float*)d_in[2];
    const float* w_hh0 = (const float*)d_in[3];
    const float* b_ih0 = (const float*)d_in[4];
    const float* b_hh0 = (const float*)d_in[5];
    const float* w_ih1 = (const float*)d_in[6];
    const float* w_hh1 = (const float*)d_in[7];
    const float* b_ih1 = (const float*)d_in[8];
    const float* b_hh1 = (const float*)d_in[9];
    const float* fc_w  = (const float*)d_in[10];
    const float* fc_b  = (const float*)d_in[11];
    float* out = (float*)d_out;

    float *x0, *xg, *h1, *last; int* sl;
    __nv_bfloat16 *ahi, *alo, *whi, *wlo;
    cudaGetSymbolAddress((void**)&x0, g_x0);
    cudaGetSymbolAddress((void**)&xg, g_xg);
    cudaGetSymbolAddress((void**)&h1, g_h1);
    cudaGetSymbolAddress((void**)&last, g_last);
    cudaGetSymbolAddress((void**)&sl, g_seqlen);
    cudaGetSymbolAddress((void**)&ahi, g_ahi);
    cudaGetSymbolAddress((void**)&alo, g_alo);
    cudaGetSymbolAddress((void**)&whi, g_whi);
    cudaGetSymbolAddress((void**)&wlo, g_wlo);

    const int REC_SMEM = 204800;
    static int once = 0;
    if (!once) {
        cudaFuncSetAttribute(lstm_rec, cudaFuncAttributeMaxDynamicSharedMemorySize, REC_SMEM);
        once = 1;
    }

    seqlen_kernel<<<B, 256>>>(feat, sl);
    embed_kernel<<<B * T, E / 4>>>(feat, emb, x0);

    // layer 0
    split4<<<(B * T * E) / 1024, 256>>>(x0, ahi, alo);
    split4<<<(G4 * E) / 1024, 256>>>(w_ih0, whi, wlo);
    gemm_mma<<<dim3(G4 / 64, (B * T) / 128), 256>>>(ahi, alo, whi, wlo,
                                                    b_ih0, b_hh0, xg, G4, E);
    lstm_rec<<<128, 256, REC_SMEM>>>(xg, w_hh0, h1, sl, nullptr);

    // layer 1
    split4<<<(B * T * H) / 1024, 256>>>(h1, ahi, alo);
    split4<<<(G4 * H) / 1024, 256>>>(w_ih1, whi, wlo);
    gemm_mma<<<dim3(G4 / 64, (B * T) / 128), 256>>>(ahi, alo, whi, wlo,
                                                    b_ih1, b_hh1, xg, G4, H);
    lstm_rec<<<128, 256, REC_SMEM>>>(xg, w_hh1, nullptr, sl, last);

    gemm_tn<<<dim3(NC / 64, 1), 256>>>(last, H, fc_w, H, fc_b, out, NC, H);
}

// round 13
// speedup vs baseline: 2.8944x; 1.0150x over previous
#include <cuda_runtime.h>
#include <cuda_bf16.h>
#include <cstdint>
#include <math.h>

#define B   64
#define T   512
#define E   512
#define H   1024
#define G4  4096
#define NC  32000
#define VOCABM1 31999

typedef unsigned long long ull;

__device__ __align__(16) float g_x0[(size_t)B * T * E];
__device__ __align__(16) float g_xg[(size_t)B * T * G4];
__device__ __align__(16) float g_h1[(size_t)B * T * H];
__device__ __align__(16) float g_last[(size_t)B * H];
__device__ __align__(16) __nv_bfloat16 g_ahi[(size_t)B * T * H];
__device__ __align__(16) __nv_bfloat16 g_alo[(size_t)B * T * H];
__device__ __align__(16) __nv_bfloat16 g_whi[(size_t)G4 * H];
__device__ __align__(16) __nv_bfloat16 g_wlo[(size_t)G4 * H];
// h ping-pong, packed mma-tile layout: [slot][kt 64][b 64][kk 16]
__device__ __align__(16) __nv_bfloat16 g_hH[2 * 64 * 64 * 16];
__device__ __align__(16) __nv_bfloat16 g_hL[2 * 64 * 64 * 16];
__device__ int g_seqlen[B];
__device__ unsigned g_bar_count, g_bar_gen;

__device__ __forceinline__ float sigm(float x) { return 1.f / (1.f + expf(-x)); }
__device__ __forceinline__ uint32_t s2u(const void* p) {
    uint32_t a;
    asm("{ .reg .u64 t; cvta.to.shared.u64 t, %1; cvt.u32.u64 %0, t; }" : "=r"(a) : "l"(p));
    return a;
}
__device__ __forceinline__ void mma16816(float* c, const uint32_t* a, uint32_t b0, uint32_t b1) {
    asm volatile(
        "mma.sync.aligned.m16n8k16.row.col.f32.bf16.bf16.f32 "
        "{%0,%1,%2,%3}, {%4,%5,%6,%7}, {%8,%9}, {%0,%1,%2,%3};"
        : "+f"(c[0]), "+f"(c[1]), "+f"(c[2]), "+f"(c[3])
        : "r"(a[0]), "r"(a[1]), "r"(a[2]), "r"(a[3]), "r"(b0), "r"(b1));
}
__device__ __forceinline__ void ldsm4(uint32_t* r, uint32_t addr) {
    asm volatile("ldmatrix.sync.aligned.m8n8.x4.shared.b16 {%0,%1,%2,%3}, [%4];"
                 : "=r"(r[0]), "=r"(r[1]), "=r"(r[2]), "=r"(r[3]) : "r"(addr));
}

__global__ void seqlen_kernel(const int* __restrict__ feat, int* __restrict__ out) {
    int b = blockIdx.x, tid = threadIdx.x, cnt = 0;
    for (int t = tid; t < T; t += 256) cnt += (feat[b * T + t] != VOCABM1);
    __shared__ int s[256];
    s[tid] = cnt; __syncthreads();
    for (int o = 128; o > 0; o >>= 1) { if (tid < o) s[tid] += s[tid + o]; __syncthreads(); }
    if (tid == 0) out[b] = s[0] - 1;
}

__global__ void embed_kernel(const int* __restrict__ feat, const float* __restrict__ emb,
                             float* __restrict__ x0) {
    int bt = blockIdx.x;
    int f = feat[bt];
    ((float4*)(x0 + (size_t)bt * E))[threadIdx.x] =
        ((const float4*)(emb + (size_t)f * E))[threadIdx.x];
}

__global__ void split4(const float* __restrict__ src, __nv_bfloat16* __restrict__ hi,
                       __nv_bfloat16* __restrict__ lo) {
    size_t i = ((size_t)blockIdx.x * 256 + threadIdx.x) * 4;
    float4 v = *(const float4*)(src + i);
    __nv_bfloat16 h0 = __float2bfloat16(v.x), h1 = __float2bfloat16(v.y);
    __nv_bfloat16 h2 = __float2bfloat16(v.z), h3 = __float2bfloat16(v.w);
    __nv_bfloat16 l0 = __float2bfloat16(v.x - __bfloat162float(h0));
    __nv_bfloat16 l1 = __float2bfloat16(v.y - __bfloat162float(h1));
    __nv_bfloat16 l2 = __float2bfloat16(v.z - __bfloat162float(h2));
    __nv_bfloat16 l3 = __float2bfloat16(v.w - __bfloat162float(h3));
    *(__nv_bfloat162*)(hi + i)     = __nv_bfloat162(h0, h1);
    *(__nv_bfloat162*)(hi + i + 2) = __nv_bfloat162(h2, h3);
    *(__nv_bfloat162*)(lo + i)     = __nv_bfloat162(l0, l1);
    *(__nv_bfloat162*)(lo + i + 2) = __nv_bfloat162(l2, l3);
}

// ---- tensor-core TN GEMM with 3-term bf16 split + register-staged double buffer ----
__global__ void __launch_bounds__(256)
gemm_mma(const __nv_bfloat16* __restrict__ Ahi, const __nv_bfloat16* __restrict__ Alo,
         const __nv_bfloat16* __restrict__ Whi, const __nv_bfloat16* __restrict__ Wlo,
         const float* __restrict__ b1, const float* __restrict__ b2,
         float* __restrict__ C, int ldc, int K) {
    __shared__ __nv_bfloat16 sAh[128 * 16], sAl[128 * 16];
    __shared__ __nv_bfloat16 sBh[64 * 16],  sBl[64 * 16];

    const int tid = threadIdx.x, lane = tid & 31, wid = tid >> 5;
    const int m0 = blockIdx.y * 128, n0 = blockIdx.x * 64;
    const int wm = (wid & 3) * 32, wn = (wid >> 2) * 32;

    const int lrow = tid >> 1, lk = (tid & 1) * 8;
    const __nv_bfloat16* Aph = Ahi + (size_t)(m0 + lrow) * K + lk;
    const __nv_bfloat16* Apl = Alo + (size_t)(m0 + lrow) * K + lk;
    const int bsel = tid >> 7, brow = (tid >> 1) & 63, bk = (tid & 1) * 8;
    const __nv_bfloat16* Bp = (bsel ? Wlo : Whi) + (size_t)(n0 + brow) * K + bk;
    __nv_bfloat16* sB = bsel ? sBl : sBh;

    const uint32_t aOff = (uint32_t)((wm + ((lane >> 3) & 1) * 8 + (lane & 7)) * 32 +
                                     (lane >> 4) * 16);
    const uint32_t bOff = (uint32_t)((wn + (lane >> 4) * 8 + (lane & 7)) * 32 +
                                     ((lane >> 3) & 1) * 16);
    const uint32_t uAh = s2u(sAh), uAl = s2u(sAl), uBh = s2u(sBh), uBl = s2u(sBl);

    float acc[2][4][4];
#pragma unroll
    for (int i = 0; i < 2; i++)
#pragma unroll
        for (int j = 0; j < 4; j++)
#pragma unroll
            for (int l = 0; l < 4; l++) acc[i][j][l] = 0.f;

    uint4 ra = *(const uint4*)(Aph);
    uint4 rl = *(const uint4*)(Apl);
    uint4 rb = *(const uint4*)(Bp);

    for (int kt = 0; kt < K; kt += 16) {
        *(uint4*)&sAh[lrow * 16 + lk] = ra;
        *(uint4*)&sAl[lrow * 16 + lk] = rl;
        *(uint4*)&sB[brow * 16 + bk]  = rb;
        __syncthreads();

        if (kt + 16 < K) {
            ra = *(const uint4*)(Aph + kt + 16);
            rl = *(const uint4*)(Apl + kt + 16);
            rb = *(const uint4*)(Bp + kt + 16);
        }

        uint32_t ah[2][4], al[2][4], bh[2][4], bl[2][4];
#pragma unroll
        for (int mt = 0; mt < 2; mt++) {
            ldsm4(ah[mt], uAh + aOff + mt * 512);
            ldsm4(al[mt], uAl + aOff + mt * 512);
        }
#pragma unroll
        for (int g = 0; g < 2; g++) {
            ldsm4(bh[g], uBh + bOff + g * 512);
            ldsm4(bl[g], uBl + bOff + g * 512);
        }
#pragma unroll
        for (int mt = 0; mt < 2; mt++)
#pragma unroll
            for (int nt = 0; nt < 4; nt++) {
                uint32_t h0 = bh[nt >> 1][(nt & 1) * 2], h1 = bh[nt >> 1][(nt & 1) * 2 + 1];
                uint32_t l0 = bl[nt >> 1][(nt & 1) * 2], l1 = bl[nt >> 1][(nt & 1) * 2 + 1];
                mma16816(acc[mt][nt], ah[mt], h0, h1);
                mma16816(acc[mt][nt], ah[mt], l0, l1);
                mma16816(acc[mt][nt], al[mt], h0, h1);
            }
        __syncthreads();
    }

    const int r = lane >> 2, cn = (lane & 3) * 2;
#pragma unroll
    for (int mt = 0; mt < 2; mt++)
#pragma unroll
        for (int nt = 0; nt < 4; nt++) {
            int n = n0 + wn + nt * 8 + cn;
            float bb0 = b1[n] + b2[n], bb1 = b1[n + 1] + b2[n + 1];
            int m = m0 + wm + mt * 16 + r;
            float* c = acc[mt][nt];
            *(float2*)&C[(size_t)m * ldc + n]       = make_float2(c[0] + bb0, c[1] + bb1);
            *(float2*)&C[(size_t)(m + 8) * ldc + n] = make_float2(c[2] + bb0, c[3] + bb1);
        }
}

// ---- scalar TN GEMM for FC head ----
__global__ void gemm_tn(const float* __restrict__ A, long lda,
                        const float* __restrict__ W, int ldw,
                        const float* __restrict__ b1,
                        float* __restrict__ C, int ldc, int K) {
    __shared__ float As[16][68];
    __shared__ float Bs[16][68];
    const int tid = threadIdx.x;
    const int m0 = blockIdx.y * 64, n0 = blockIdx.x * 64;
    const float* Ap = A + (long)m0 * lda;
    const float* Wp = W + (long)n0 * ldw;
    const int lr = tid >> 2, lk = (tid & 3) * 4, ty = tid >> 4, tx = tid & 15;
    float acc[4][4];
#pragma unroll
    for (int i = 0; i < 4; i++)
#pragma unroll
        for (int j = 0; j < 4; j++) acc[i][j] = 0.f;
    for (int kt = 0; kt < K; kt += 16) {
        float4 a4 = *(const float4*)(Ap + (long)lr * lda + kt + lk);
        float4 w4 = *(const float4*)(Wp + (long)lr * ldw + kt + lk);
        As[lk + 0][lr] = a4.x; As[lk + 1][lr] = a4.y;
        As[lk + 2][lr] = a4.z; As[lk + 3][lr] = a4.w;
        Bs[lk + 0][lr] = w4.x; Bs[lk + 1][lr] = w4.y;
        Bs[lk + 2][lr] = w4.z; Bs[lk + 3][lr] = w4.w;
        __syncthreads();
#pragma unroll
        for (int kk = 0; kk < 16; kk++) {
            float4 a = *(const float4*)&As[kk][ty * 4];
            float4 b = *(const float4*)&Bs[kk][tx * 4];
            acc[0][0] += a.x*b.x; acc[0][1] += a.x*b.y; acc[0][2] += a.x*b.z; acc[0][3] += a.x*b.w;
            acc[1][0] += a.y*b.x; acc[1][1] += a.y*b.y; acc[1][2] += a.y*b.z; acc[1][3] += a.y*b.w;
            acc[2][0] += a.z*b.x; acc[2][1] += a.z*b.y; acc[2][2] += a.z*b.z; acc[2][3] += a.z*b.w;
            acc[3][0] += a.w*b.x; acc[3][1] += a.w*b.y; acc[3][2] += a.w*b.z; acc[3][3] += a.w*b.w;
        }
        __syncthreads();
    }
#pragma unroll
    for (int i = 0; i < 4; i++)
#pragma unroll
        for (int j = 0; j < 4; j++) {
            int n = n0 + tx * 4 + j;
            C[(long)(m0 + ty * 4 + i) * ldc + n] = acc[i][j] + b1[n];
        }
}

// ---- persistent tensor-core LSTM recurrence (6 independent mma chains) ----
extern __shared__ char rsm[];
__global__ void __launch_bounds__(256, 1)
lstm_rec(const float* __restrict__ xg, const float* __restrict__ w_hh,
         float* __restrict__ h1, const int* __restrict__ seqlen,
         float* __restrict__ last) {
    __nv_bfloat16* sW = (__nv_bfloat16*)rsm;              // 131072 B
    __nv_bfloat16* sA = (__nv_bfloat16*)(rsm + 131072);   // 65536 B
    float* gbuf = (float*)(rsm + 196608);                 // 8192 B

    const int tid = threadIdx.x, lane = tid & 31, wid = tid >> 5;
    const int cta = blockIdx.x;
    const int mt = wid & 3, nh = wid >> 2;

    for (int idx = tid; idx < 32 * 1024; idx += 256) {
        int nl = idx >> 10, k = idx & 1023;
        int g = nl >> 3, u = nl & 7, kt = k >> 4, kk = k & 15;
        float w = w_hh[(size_t)(g * 1024 + cta * 8 + u) * H + k];
        __nv_bfloat16 hi = __float2bfloat16(w);
        __nv_bfloat16 lo = __float2bfloat16(w - __bfloat162float(hi));
        sW[(kt * 2 + 0) * 512 + nl * 16 + kk] = hi;
        sW[(kt * 2 + 1) * 512 + nl * 16 + kk] = lo;
    }
    __syncthreads();

    const uint32_t uW = s2u(sW), uA = s2u(sA);
    const uint32_t aOff = (uint32_t)((mt * 16 + ((lane >> 3) & 1) * 8 + (lane & 7)) * 32 +
                                     (lane >> 4) * 16);
    const uint32_t bOff = (uint32_t)((nh * 16 + (lane >> 4) * 8 + (lane & 7)) * 32 +
                                     ((lane >> 3) & 1) * 16);

    const int cb = tid & 63, kp = tid >> 6, u0 = 2 * kp;
    const int myseq = seqlen[cb];
    const int khid = cta * 8 + u0;
    const int kt_h = khid >> 4, kk_h = khid & 15;
    float c_0 = 0.f, c_1 = 0.f;

    const int r = lane >> 2, cn = (lane & 3) * 2;

    for (int t = 0; t < T; t++) {
        // 3 term-separated accumulator sets x 2 n-tiles = 6 independent chains
        float aH[2][4], aM[2][4], aL[2][4];
#pragma unroll
        for (int i = 0; i < 2; i++)
#pragma unroll
            for (int j = 0; j < 4; j++) { aH[i][j] = 0.f; aM[i][j] = 0.f; aL[i][j] = 0.f; }

        if (t > 0) {
            const int sp = (t - 1) & 1;
            const uint4* gh = (const uint4*)(g_hH + sp * 65536);
            const uint4* gl = (const uint4*)(g_hL + sp * 65536);
            uint4 rg[8];
#pragma unroll
            for (int i = 0; i < 4; i++) {
                rg[i] = gh[tid + i * 256];
                rg[4 + i] = gl[tid + i * 256];
            }
#pragma unroll
            for (int i = 0; i < 4; i++) {
                ((uint4*)sA)[tid + i * 256] = rg[i];
                ((uint4*)sA)[1024 + tid + i * 256] = rg[4 + i];
            }
            __syncthreads();

            for (int ch = 0; ch < 8; ch++) {
                if (ch < 7) {
#pragma unroll
                    for (int i = 0; i < 4; i++) {
                        rg[i] = gh[(ch + 1) * 1024 + tid + i * 256];
                        rg[4 + i] = gl[(ch + 1) * 1024 + tid + i * 256];
                    }
                }
                const uint32_t abase = uA + (ch & 1) * 32768;
#pragma unroll
                for (int j = 0; j < 8; j++) {
                    const int kt = ch * 8 + j;
                    uint32_t ah[4], al[4], bh[4], bl[4];
                    ldsm4(ah, abase + j * 2048 + aOff);
                    ldsm4(al, abase + 16384 + j * 2048 + aOff);
                    ldsm4(bh, uW + kt * 2048 + bOff);
                    ldsm4(bl, uW + kt * 2048 + 1024 + bOff);
                    mma16816(aH[0], ah, bh[0], bh[1]);
                    mma16816(aM[0], ah, bl[0], bl[1]);
                    mma16816(aL[0], al, bh[0], bh[1]);
                    mma16816(aH[1], ah, bh[2], bh[3]);
                    mma16816(aM[1], ah, bl[2], bl[3]);
                    mma16816(aL[1], al, bh[2], bh[3]);
                }
                if (ch < 7) {
                    const int ob = ((ch + 1) & 1) * 2048;
#pragma unroll
                    for (int i = 0; i < 4; i++) {
                        ((uint4*)sA)[ob + tid + i * 256] = rg[i];
                        ((uint4*)sA)[ob + 1024 + tid + i * 256] = rg[4 + i];
                    }
                    __syncthreads();
                }
            }
        }

        // ---- gate mix through SMEM: gbuf[(gate*8+u)*64 + b]
#pragma unroll
        for (int ng = 0; ng < 2; ng++) {
            const int gate = nh * 2 + ng;
            float v0 = aH[ng][0] + aM[ng][0] + aL[ng][0];
            float v1 = aH[ng][1] + aM[ng][1] + aL[ng][1];
            float v2 = aH[ng][2] + aM[ng][2] + aL[ng][2];
            float v3 = aH[ng][3] + aM[ng][3] + aL[ng][3];
            gbuf[(gate * 8 + cn) * 64 + mt * 16 + r]         = v0;
            gbuf[(gate * 8 + cn + 1) * 64 + mt * 16 + r]     = v1;
            gbuf[(gate * 8 + cn) * 64 + mt * 16 + r + 8]     = v2;
            gbuf[(gate * 8 + cn + 1) * 64 + mt * 16 + r + 8] = v3;
        }
        __syncthreads();

        // ---- cell
        {
            const float* xr = xg + ((size_t)cb * T + t) * G4 + khid;
            float2 xi = *(const float2*)(xr);
            float2 xf = *(const float2*)(xr + H);
            float2 xgg = *(const float2*)(xr + 2 * H);
            float2 xo = *(const float2*)(xr + 3 * H);
            float pi0 = gbuf[(0 * 8 + u0) * 64 + cb] + xi.x;
            float pi1 = gbuf[(0 * 8 + u0 + 1) * 64 + cb] + xi.y;
            float pf0 = gbuf[(1 * 8 + u0) * 64 + cb] + xf.x;
            float pf1 = gbuf[(1 * 8 + u0 + 1) * 64 + cb] + xf.y;
            float pg0 = gbuf[(2 * 8 + u0) * 64 + cb] + xgg.x;
            float pg1 = gbuf[(2 * 8 + u0 + 1) * 64 + cb] + xgg.y;
            float po0 = gbuf[(3 * 8 + u0) * 64 + cb] + xo.x;
            float po1 = gbuf[(3 * 8 + u0 + 1) * 64 + cb] + xo.y;

            float i0 = sigm(pi0), f0 = sigm(pf0), gg0 = tanhf(pg0), o0 = sigm(po0);
            float i1 = sigm(pi1), f1 = sigm(pf1), gg1 = tanhf(pg1), o1 = sigm(po1);
            c_0 = f0 * c_0 + i0 * gg0;
            c_1 = f1 * c_1 + i1 * gg1;
            float h_0 = o0 * tanhf(c_0);
            float h_1 = o1 * tanhf(c_1);

            __nv_bfloat16 hh0 = __float2bfloat16(h_0);
            __nv_bfloat16 hh1 = __float2bfloat16(h_1);
            __nv_bfloat16 hl0 = __float2bfloat16(h_0 - __bfloat162float(hh0));
            __nv_bfloat16 hl1 = __float2bfloat16(h_1 - __bfloat162float(hh1));
            const size_t po = (size_t)((t & 1) * 4096 + kt_h * 64 + cb) * 16 + kk_h;
            *(__nv_bfloat162*)(g_hH + po) = __nv_bfloat162(hh0, hh1);
            *(__nv_bfloat162*)(g_hL + po) = __nv_bfloat162(hl0, hl1);

            if (h1)
                *(float2*)&h1[((size_t)cb * T + t) * H + khid] = make_float2(h_0, h_1);
            if (last && t == myseq)
                *(float2*)&last[(size_t)cb * H + khid] = make_float2(h_0, h_1);
        }

        // ---- grid barrier ----
        __threadfence();
        __syncthreads();
        if (tid == 0) {
            unsigned gen = *(volatile unsigned*)&g_bar_gen;
            unsigned a = atomicAdd(&g_bar_count, 1u);
            if (a == (unsigned)(gridDim.x - 1)) {
                g_bar_count = 0;
                __threadfence();
                atomicAdd(&g_bar_gen, 1u);
            } else {
                while (*(volatile unsigned*)&g_bar_gen == gen) {}
            }
        }
        __syncthreads();
    }
}

extern "C" void kernel_launch(void* const* d_in, const int* in_sizes, int n_in,
                              void* d_out, int out_size) {
    const int*   feat  = (const int*)d_in[0];
    const float* emb   = (const float*)d_in[1];
    const float* w_ih0 = (const float*)d_in[2];
    const float* w_hh0 = (const float*)d_in[3];
    const float* b_ih0 = (const float*)d_in[4];
    const float* b_hh0 = (const float*)d_in[5];
    const float* w_ih1 = (const float*)d_in[6];
    const float* w_hh1 = (const float*)d_in[7];
    const float* b_ih1 = (const float*)d_in[8];
    const float* b_hh1 = (const float*)d_in[9];
    const float* fc_w  = (const float*)d_in[10];
    const float* fc_b  = (const float*)d_in[11];
    float* out = (float*)d_out;

    float *x0, *xg, *h1, *last; int* sl;
    __nv_bfloat16 *ahi, *alo, *whi, *wlo;
    cudaGetSymbolAddress((void**)&x0, g_x0);
    cudaGetSymbolAddress((void**)&xg, g_xg);
    cudaGetSymbolAddress((void**)&h1, g_h1);
    cudaGetSymbolAddress((void**)&last, g_last);
    cudaGetSymbolAddress((void**)&sl, g_seqlen);
    cudaGetSymbolAddress((void**)&ahi, g_ahi);
    cudaGetSymbolAddress((void**)&alo, g_alo);
    cudaGetSymbolAddress((void**)&whi, g_whi);
    cudaGetSymbolAddress((void**)&wlo, g_wlo);

    const int REC_SMEM = 204800;
    static int once = 0;
    if (!once) {
        cudaFuncSetAttribute(lstm_rec, cudaFuncAttributeMaxDynamicSharedMemorySize, REC_SMEM);
        once = 1;
    }

    seqlen_kernel<<<B, 256>>>(feat, sl);
    embed_kernel<<<B * T, E / 4>>>(feat, emb, x0);

    // layer 0
    split4<<<(B * T * E) / 1024, 256>>>(x0, ahi, alo);
    split4<<<(G4 * E) / 1024, 256>>>(w_ih0, whi, wlo);
    gemm_mma<<<dim3(G4 / 64, (B * T) / 128), 256>>>(ahi, alo, whi, wlo,
                                                    b_ih0, b_hh0, xg, G4, E);
    lstm_rec<<<128, 256, REC_SMEM>>>(xg, w_hh0, h1, sl, nullptr);

    // layer 1
    split4<<<(B * T * H) / 1024, 256>>>(h1, ahi, alo);
    split4<<<(G4 * H) / 1024, 256>>>(w_ih1, whi, wlo);
    gemm_mma<<<dim3(G4 / 64, (B * T) / 128), 256>>>(ahi, alo, whi, wlo,
                                                    b_ih1, b_hh1, xg, G4, H);
    lstm_rec<<<128, 256, REC_SMEM>>>(xg, w_hh1, nullptr, sl, last);

    gemm_tn<<<dim3(NC / 64, 1), 256>>>(last, H, fc_w, H, fc_b, out, NC, H);
}

// round 17
// speedup vs baseline: 3.7535x; 1.2968x over previous
#include <cuda_runtime.h>
#include <cuda_fp16.h>
#include <cstdint>
#include <math.h>

#define B   64
#define T   512
#define E   512
#define H   1024
#define G4  4096
#define NC  32000
#define VOCABM1 31999

__device__ __align__(16) float g_x0[(size_t)B * T * E];
__device__ __align__(16) float g_xg[(size_t)B * T * G4];
__device__ __align__(16) float g_h1[(size_t)B * T * H];
__device__ __align__(16) float g_last[(size_t)B * H];
__device__ __align__(16) __half g_af[(size_t)B * T * H];   // fp16 activations
__device__ __align__(16) __half g_wh[(size_t)G4 * H];      // fp16 weight hi
__device__ __align__(16) __half g_wl[(size_t)G4 * H];      // fp16 weight lo
// h ping-pong, packed mma-tile layout: [slot][kt 64][b 64][kk 16], single fp16
__device__ __align__(16) __half g_hF[2 * 64 * 64 * 16];
__device__ int g_seqlen[B];
__device__ unsigned g_bar_count, g_bar_gen;

__device__ __forceinline__ float sigm(float x) { return 1.f / (1.f + expf(-x)); }
__device__ __forceinline__ uint32_t s2u(const void* p) {
    uint32_t a;
    asm("{ .reg .u64 t; cvta.to.shared.u64 t, %1; cvt.u32.u64 %0, t; }" : "=r"(a) : "l"(p));
    return a;
}
__device__ __forceinline__ void mmaf16(float* c, const uint32_t* a, uint32_t b0, uint32_t b1) {
    asm volatile(
        "mma.sync.aligned.m16n8k16.row.col.f32.f16.f16.f32 "
        "{%0,%1,%2,%3}, {%4,%5,%6,%7}, {%8,%9}, {%0,%1,%2,%3};"
        : "+f"(c[0]), "+f"(c[1]), "+f"(c[2]), "+f"(c[3])
        : "r"(a[0]), "r"(a[1]), "r"(a[2]), "r"(a[3]), "r"(b0), "r"(b1));
}
__device__ __forceinline__ void ldsm4(uint32_t* r, uint32_t addr) {
    asm volatile("ldmatrix.sync.aligned.m8n8.x4.shared.b16 {%0,%1,%2,%3}, [%4];"
                 : "=r"(r[0]), "=r"(r[1]), "=r"(r[2]), "=r"(r[3]) : "r"(addr));
}

__global__ void seqlen_kernel(const int* __restrict__ feat, int* __restrict__ out) {
    int b = blockIdx.x, tid = threadIdx.x, cnt = 0;
    for (int t = tid; t < T; t += 256) cnt += (feat[b * T + t] != VOCABM1);
    __shared__ int s[256];
    s[tid] = cnt; __syncthreads();
    for (int o = 128; o > 0; o >>= 1) { if (tid < o) s[tid] += s[tid + o]; __syncthreads(); }
    if (tid == 0) out[b] = s[0] - 1;
}

__global__ void embed_kernel(const int* __restrict__ feat, const float* __restrict__ emb,
                             float* __restrict__ x0) {
    int bt = blockIdx.x;
    int f = feat[bt];
    ((float4*)(x0 + (size_t)bt * E))[threadIdx.x] =
        ((const float4*)(emb + (size_t)f * E))[threadIdx.x];
}

// fp32 -> fp16 (activations, single term)
__global__ void cvtA4(const float* __restrict__ src, __half* __restrict__ dst) {
    size_t i = ((size_t)blockIdx.x * 256 + threadIdx.x) * 4;
    float4 v = *(const float4*)(src + i);
    *(__half2*)(dst + i)     = __floats2half2_rn(v.x, v.y);
    *(__half2*)(dst + i + 2) = __floats2half2_rn(v.z, v.w);
}

// fp32 -> fp16 hi + fp16 lo (weights, exact 2-term split)
__global__ void splitW4(const float* __restrict__ src, __half* __restrict__ hi,
                        __half* __restrict__ lo) {
    size_t i = ((size_t)blockIdx.x * 256 + threadIdx.x) * 4;
    float4 v = *(const float4*)(src + i);
    __half h0 = __float2half_rn(v.x), h1 = __float2half_rn(v.y);
    __half h2 = __float2half_rn(v.z), h3 = __float2half_rn(v.w);
    __half l0 = __float2half_rn(v.x - __half2float(h0));
    __half l1 = __float2half_rn(v.y - __half2float(h1));
    __half l2 = __float2half_rn(v.z - __half2float(h2));
    __half l3 = __float2half_rn(v.w - __half2float(h3));
    *(__half2*)(hi + i)     = __halves2half2(h0, h1);
    *(__half2*)(hi + i + 2) = __halves2half2(h2, h3);
    *(__half2*)(lo + i)     = __halves2half2(l0, l1);
    *(__half2*)(lo + i + 2) = __halves2half2(l2, l3);
}

// ---- tensor-core TN GEMM, fp16 2-term: C = A*(Wh+Wl) + b1 + b2 ----
// block tile 128m x 64n, 8 warps (4m x 2n), warp tile 32x32, BK=16.
__global__ void __launch_bounds__(256)
gemm_mma2(const __half* __restrict__ Af,
          const __half* __restrict__ Whi, const __half* __restrict__ Wlo,
          const float* __restrict__ b1, const float* __restrict__ b2,
          float* __restrict__ C, int ldc, int K) {
    __shared__ __half sA[128 * 16];
    __shared__ __half sBh[64 * 16], sBl[64 * 16];

    const int tid = threadIdx.x, lane = tid & 31, wid = tid >> 5;
    const int m0 = blockIdx.y * 128, n0 = blockIdx.x * 64;
    const int wm = (wid & 3) * 32, wn = (wid >> 2) * 32;

    const int lrow = tid >> 1, lk = (tid & 1) * 8;
    const __half* Ap = Af + (size_t)(m0 + lrow) * K + lk;
    const int bsel = tid >> 7, brow = (tid >> 1) & 63, bk = (tid & 1) * 8;
    const __half* Bp = (bsel ? Wlo : Whi) + (size_t)(n0 + brow) * K + bk;
    __half* sB = bsel ? sBl : sBh;

    const uint32_t aOff = (uint32_t)((wm + ((lane >> 3) & 1) * 8 + (lane & 7)) * 32 +
                                     (lane >> 4) * 16);
    const uint32_t bOff = (uint32_t)((wn + (lane >> 4) * 8 + (lane & 7)) * 32 +
                                     ((lane >> 3) & 1) * 16);
    const uint32_t uA = s2u(sA), uBh = s2u(sBh), uBl = s2u(sBl);

    float accP[2][4][4], accQ[2][4][4];
#pragma unroll
    for (int i = 0; i < 2; i++)
#pragma unroll
        for (int j = 0; j < 4; j++)
#pragma unroll
            for (int l = 0; l < 4; l++) { accP[i][j][l] = 0.f; accQ[i][j][l] = 0.f; }

    uint4 ra = *(const uint4*)(Ap);
    uint4 rb = *(const uint4*)(Bp);

    for (int kt = 0; kt < K; kt += 16) {
        *(uint4*)&sA[lrow * 16 + lk] = ra;
        *(uint4*)&sB[brow * 16 + bk] = rb;
        __syncthreads();

        if (kt + 16 < K) {
            ra = *(const uint4*)(Ap + kt + 16);
            rb = *(const uint4*)(Bp + kt + 16);
        }

        uint32_t ah[2][4], bh[2][4], bl[2][4];
#pragma unroll
        for (int mt = 0; mt < 2; mt++) ldsm4(ah[mt], uA + aOff + mt * 512);
#pragma unroll
        for (int g = 0; g < 2; g++) {
            ldsm4(bh[g], uBh + bOff + g * 512);
            ldsm4(bl[g], uBl + bOff + g * 512);
        }
#pragma unroll
        for (int mt = 0; mt < 2; mt++)
#pragma unroll
            for (int nt = 0; nt < 4; nt++) {
                uint32_t h0 = bh[nt >> 1][(nt & 1) * 2], h1 = bh[nt >> 1][(nt & 1) * 2 + 1];
                uint32_t l0 = bl[nt >> 1][(nt & 1) * 2], l1 = bl[nt >> 1][(nt & 1) * 2 + 1];
                mmaf16(accP[mt][nt], ah[mt], h0, h1);
                mmaf16(accQ[mt][nt], ah[mt], l0, l1);
            }
        __syncthreads();
    }

    const int r = lane >> 2, cn = (lane & 3) * 2;
#pragma unroll
    for (int mt = 0; mt < 2; mt++)
#pragma unroll
        for (int nt = 0; nt < 4; nt++) {
            int n = n0 + wn + nt * 8 + cn;
            float bb0 = b1[n] + b2[n], bb1 = b1[n + 1] + b2[n + 1];
            int m = m0 + wm + mt * 16 + r;
            float* p = accP[mt][nt];
            float* q = accQ[mt][nt];
            *(float2*)&C[(size_t)m * ldc + n] =
                make_float2(p[0] + q[0] + bb0, p[1] + q[1] + bb1);
            *(float2*)&C[(size_t)(m + 8) * ldc + n] =
                make_float2(p[2] + q[2] + bb0, p[3] + q[3] + bb1);
        }
}

// ---- scalar TN GEMM for FC head ----
__global__ void gemm_tn(const float* __restrict__ A, long lda,
                        const float* __restrict__ W, int ldw,
                        const float* __restrict__ b1,
                        float* __restrict__ C, int ldc, int K) {
    __shared__ float As[16][68];
    __shared__ float Bs[16][68];
    const int tid = threadIdx.x;
    const int m0 = blockIdx.y * 64, n0 = blockIdx.x * 64;
    const float* Ap = A + (long)m0 * lda;
    const float* Wp = W + (long)n0 * ldw;
    const int lr = tid >> 2, lk = (tid & 3) * 4, ty = tid >> 4, tx = tid & 15;
    float acc[4][4];
#pragma unroll
    for (int i = 0; i < 4; i++)
#pragma unroll
        for (int j = 0; j < 4; j++) acc[i][j] = 0.f;
    for (int kt = 0; kt < K; kt += 16) {
        float4 a4 = *(const float4*)(Ap + (long)lr * lda + kt + lk);
        float4 w4 = *(const float4*)(Wp + (long)lr * ldw + kt + lk);
        As[lk + 0][lr] = a4.x; As[lk + 1][lr] = a4.y;
        As[lk + 2][lr] = a4.z; As[lk + 3][lr] = a4.w;
        Bs[lk + 0][lr] = w4.x; Bs[lk + 1][lr] = w4.y;
        Bs[lk + 2][lr] = w4.z; Bs[lk + 3][lr] = w4.w;
        __syncthreads();
#pragma unroll
        for (int kk = 0; kk < 16; kk++) {
            float4 a = *(const float4*)&As[kk][ty * 4];
            float4 b = *(const float4*)&Bs[kk][tx * 4];
            acc[0][0] += a.x*b.x; acc[0][1] += a.x*b.y; acc[0][2] += a.x*b.z; acc[0][3] += a.x*b.w;
            acc[1][0] += a.y*b.x; acc[1][1] += a.y*b.y; acc[1][2] += a.y*b.z; acc[1][3] += a.y*b.w;
            acc[2][0] += a.z*b.x; acc[2][1] += a.z*b.y; acc[2][2] += a.z*b.z; acc[2][3] += a.z*b.w;
            acc[3][0] += a.w*b.x; acc[3][1] += a.w*b.y; acc[3][2] += a.w*b.z; acc[3][3] += a.w*b.w;
        }
        __syncthreads();
    }
#pragma unroll
    for (int i = 0; i < 4; i++)
#pragma unroll
        for (int j = 0; j < 4; j++) {
            int n = n0 + tx * 4 + j;
            C[(long)(m0 + ty * 4 + i) * ldc + n] = acc[i][j] + b1[n];
        }
}

// ---- persistent tensor-core LSTM recurrence (fp16 2-term) ----
// 128 CTAs x 256 thr (8 warps). CTA owns hidden units [8c,8c+8) across 4 gates.
// SMEM: sW [64kt][2term][32n][16k] half = 128KB | sA [2buf][8j][64b][16k] half = 32KB
//     | gbuf [4g][8u][64b] f32 = 8KB.  Total 172032 B.
extern __shared__ char rsm[];
__global__ void __launch_bounds__(256, 1)
lstm_rec(const float* __restrict__ xg, const float* __restrict__ w_hh,
         float* __restrict__ h1, const int* __restrict__ seqlen,
         float* __restrict__ last) {
    __half* sW = (__half*)rsm;                 // 131072 B
    __half* sA = (__half*)(rsm + 131072);      // 32768 B
    float* gbuf = (float*)(rsm + 163840);      // 8192 B

    const int tid = threadIdx.x, lane = tid & 31, wid = tid >> 5;
    const int cta = blockIdx.x;
    const int mt = wid & 3, nh = wid >> 2;

    // stage weight slice: rows nl = g*8+u -> w_hh[g*1024 + cta*8 + u][k], fp16 hi/lo
    for (int idx = tid; idx < 32 * 1024; idx += 256) {
        int nl = idx >> 10, k = idx & 1023;
        int kt = k >> 4, kk = k & 15;
        float w = w_hh[(size_t)((nl >> 3) * 1024 + cta * 8 + (nl & 7)) * H + k];
        __half hi = __float2half_rn(w);
        __half lo = __float2half_rn(w - __half2float(hi));
        sW[(kt * 2 + 0) * 512 + nl * 16 + kk] = hi;
        sW[(kt * 2 + 1) * 512 + nl * 16 + kk] = lo;
    }
    __syncthreads();

    const uint32_t uW = s2u(sW), uA = s2u(sA);
    const uint32_t aOff = (uint32_t)((mt * 16 + ((lane >> 3) & 1) * 8 + (lane & 7)) * 32 +
                                     (lane >> 4) * 16);
    const uint32_t bOff = (uint32_t)((nh * 16 + (lane >> 4) * 8 + (lane & 7)) * 32 +
                                     ((lane >> 3) & 1) * 16);

    const int cb = tid & 63, kp = tid >> 6, u0 = 2 * kp;
    const int myseq = seqlen[cb];
    const int khid = cta * 8 + u0;
    const int kt_h = khid >> 4, kk_h = khid & 15;
    float c_0 = 0.f, c_1 = 0.f;

    const int r = lane >> 2, cn = (lane & 3) * 2;

    for (int t = 0; t < T; t++) {
        float accP[2][4], accQ[2][4];
#pragma unroll
        for (int i = 0; i < 2; i++)
#pragma unroll
            for (int j = 0; j < 4; j++) { accP[i][j] = 0.f; accQ[i][j] = 0.f; }

        if (t > 0) {
            const int sp = (t - 1) & 1;
            const uint4* gh = (const uint4*)(g_hF + sp * 65536);
            uint4 rg[4];
#pragma unroll
            for (int i = 0; i < 4; i++) rg[i] = gh[tid + i * 256];
#pragma unroll
            for (int i = 0; i < 4; i++) ((uint4*)sA)[tid + i * 256] = rg[i];
            __syncthreads();

            for (int ch = 0; ch < 8; ch++) {
                if (ch < 7) {
#pragma unroll
                    for (int i = 0; i < 4; i++)
                        rg[i] = gh[(ch + 1) * 1024 + tid + i * 256];
                }
                const uint32_t abase = uA + (ch & 1) * 16384;
#pragma unroll
                for (int j = 0; j < 8; j++) {
                    const int kt = ch * 8 + j;
                    uint32_t a[4], bh[4], bl[4];
                    ldsm4(a, abase + j * 2048 + aOff);
                    ldsm4(bh, uW + kt * 2048 + bOff);
                    ldsm4(bl, uW + kt * 2048 + 1024 + bOff);
                    mmaf16(accP[0], a, bh[0], bh[1]);
                    mmaf16(accQ[0], a, bl[0], bl[1]);
                    mmaf16(accP[1], a, bh[2], bh[3]);
                    mmaf16(accQ[1], a, bl[2], bl[3]);
                }
                if (ch < 7) {
                    const int ob = ((ch + 1) & 1) * 1024;
#pragma unroll
                    for (int i = 0; i < 4; i++) ((uint4*)sA)[ob + tid + i * 256] = rg[i];
                    __syncthreads();
                }
            }
        }

        // gate mix through SMEM: gbuf[(gate*8+u)*64 + b]
#pragma unroll
        for (int ng = 0; ng < 2; ng++) {
            const int gate = nh * 2 + ng;
            float v0 = accP[ng][0] + accQ[ng][0];
            float v1 = accP[ng][1] + accQ[ng][1];
            float v2 = accP[ng][2] + accQ[ng][2];
            float v3 = accP[ng][3] + accQ[ng][3];
            gbuf[(gate * 8 + cn) * 64 + mt * 16 + r]         = v0;
            gbuf[(gate * 8 + cn + 1) * 64 + mt * 16 + r]     = v1;
            gbuf[(gate * 8 + cn) * 64 + mt * 16 + r + 8]     = v2;
            gbuf[(gate * 8 + cn + 1) * 64 + mt * 16 + r + 8] = v3;
        }
        __syncthreads();

        // cell: thread -> (batch cb, units khid, khid+1)
        {
            const float* xr = xg + ((size_t)cb * T + t) * G4 + khid;
            float2 xi = *(const float2*)(xr);
            float2 xf = *(const float2*)(xr + H);
            float2 xgg = *(const float2*)(xr + 2 * H);
            float2 xo = *(const float2*)(xr + 3 * H);
            float pi0 = gbuf[(0 * 8 + u0) * 64 + cb] + xi.x;
            float pi1 = gbuf[(0 * 8 + u0 + 1) * 64 + cb] + xi.y;
            float pf0 = gbuf[(1 * 8 + u0) * 64 + cb] + xf.x;
            float pf1 = gbuf[(1 * 8 + u0 + 1) * 64 + cb] + xf.y;
            float pg0 = gbuf[(2 * 8 + u0) * 64 + cb] + xgg.x;
            float pg1 = gbuf[(2 * 8 + u0 + 1) * 64 + cb] + xgg.y;
            float po0 = gbuf[(3 * 8 + u0) * 64 + cb] + xo.x;
            float po1 = gbuf[(3 * 8 + u0 + 1) * 64 + cb] + xo.y;

            float i0 = sigm(pi0), f0 = sigm(pf0), gg0 = tanhf(pg0), o0 = sigm(po0);
            float i1 = sigm(pi1), f1 = sigm(pf1), gg1 = tanhf(pg1), o1 = sigm(po1);
            c_0 = f0 * c_0 + i0 * gg0;
            c_1 = f1 * c_1 + i1 * gg1;
            float h_0 = o0 * tanhf(c_0);
            float h_1 = o1 * tanhf(c_1);

            const size_t po = (size_t)((t & 1) * 4096 + kt_h * 64 + cb) * 16 + kk_h;
            *(__half2*)(g_hF + po) = __floats2half2_rn(h_0, h_1);

            if (h1)
                *(float2*)&h1[((size_t)cb * T + t) * H + khid] = make_float2(h_0, h_1);
            if (last && t == myseq)
                *(float2*)&last[(size_t)cb * H + khid] = make_float2(h_0, h_1);
        }

        // grid barrier (sense-reversal)
        __threadfence();
        __syncthreads();
        if (tid == 0) {
            unsigned gen = *(volatile unsigned*)&g_bar_gen;
            unsigned a = atomicAdd(&g_bar_count, 1u);
            if (a == (unsigned)(gridDim.x - 1)) {
                g_bar_count = 0;
                __threadfence();
                atomicAdd(&g_bar_gen, 1u);
            } else {
                while (*(volatile unsigned*)&g_bar_gen == gen) {}
            }
        }
        __syncthreads();
    }
}

extern "C" void kernel_launch(void* const* d_in, const int* in_sizes, int n_in,
                              void* d_out, int out_size) {
    const int*   feat  = (const int*)d_in[0];
    const float* emb   = (const float*)d_in[1];
    const float* w_ih0 = (const float*)d_in[2];
    const float* w_hh0 = (const float*)d_in[3];
    const float* b_ih0 = (const float*)d_in[4];
    const float* b_hh0 = (const float*)d_in[5];
    const float* w_ih1 = (const float*)d_in[6];
    const float* w_hh1 = (const float*)d_in[7];
    const float* b_ih1 = (const float*)d_in[8];
    const float* b_hh1 = (const float*)d_in[9];
    const float* fc_w  = (const float*)d_in[10];
    const float* fc_b  = (const float*)d_in[11];
    float* out = (float*)d_out;

    float *x0, *xg, *h1, *last; int* sl;
    __half *af, *wh, *wl;
    cudaGetSymbolAddress((void**)&x0, g_x0);
    cudaGetSymbolAddress((void**)&xg, g_xg);
    cudaGetSymbolAddress((void**)&h1, g_h1);
    cudaGetSymbolAddress((void**)&last, g_last);
    cudaGetSymbolAddress((void**)&sl, g_seqlen);
    cudaGetSymbolAddress((void**)&af, g_af);
    cudaGetSymbolAddress((void**)&wh, g_wh);
    cudaGetSymbolAddress((void**)&wl, g_wl);

    const int REC_SMEM = 172032;
    static int once = 0;
    if (!once) {
        cudaFuncSetAttribute(lstm_rec, cudaFuncAttributeMaxDynamicSharedMemorySize, REC_SMEM);
        once = 1;
    }

    seqlen_kernel<<<B, 256>>>(feat, sl);
    embed_kernel<<<B * T, E / 4>>>(feat, emb, x0);

    // layer 0
    cvtA4<<<(B * T * E) / 1024, 256>>>(x0, af);
    splitW4<<<(G4 * E) / 1024, 256>>>(w_ih0, wh, wl);
    gemm_mma2<<<dim3(G4 / 64, (B * T) / 128), 256>>>(af, wh, wl, b_ih0, b_hh0, xg, G4, E);
    lstm_rec<<<128, 256, REC_SMEM>>>(xg, w_hh0, h1, sl, nullptr);

    // layer 1
    cvtA4<<<(B * T * H) / 1024, 256>>>(h1, af);
    splitW4<<<(G4 * H) / 1024, 256>>>(w_ih1, wh, wl);
    gemm_mma2<<<dim3(G4 / 64, (B * T) / 128), 256>>>(af, wh, wl, b_ih1, b_hh1, xg, G4, H);
    lstm_rec<<<128, 256, REC_SMEM>>>(xg, w_hh1, nullptr, sl, last);

    gemm_tn<<<dim3(NC / 64, 1), 256>>>(last, H, fc_w, H, fc_b, out, NC, H);
}